// round 14
// baseline (speedup 1.0000x reference)
#include <cuda_runtime.h>
#include <cuda_fp16.h>
#include <math_constants.h>
#include <cstdint>

#define B_SZ  2048
#define FEAT  840
#define HID   256
#define LAT   128
#define NQ    12
#define NEMB  512
#define KTOT  768

#define NT        7
#define TILE_T    128
#define TILES_TOT (B_SZ*NT)           /* 14336 */
#define NCHK      24
#define CHUNK_U32 4096                /* B frag words per chunk */
#define NBFRAG    (NCHK*CHUNK_U32)    /* 98304 */

#define MARGIN 3e-6f

typedef unsigned long long ull;

// ----------------------------- device scratch ------------------------------
__device__ __align__(16) uint32_t g_Bfrag[NBFRAG];   // w2 fp16 2-split frags
__device__ __align__(16) float g_w2t[KTOT*LAT];      // exact path [(k*256+c)][l]
__device__ float  g_cnorm[NQ*NEMB];
__device__ double g_zpart[(size_t)TILES_TOT*LAT];
__device__ __align__(16) float g_z[B_SZ*LAT];
__device__ int g_flagcnt;
__device__ int g_flaglist[B_SZ];

__device__ __forceinline__ float fp16_split_val(float v, int split){
    float h = __half2float(__float2half_rn(v));
    if (split == 0) return h;
    return v - h;
}

__device__ __forceinline__ void mma_fp16(float* d, const uint32_t* a, const uint32_t* b){
    asm volatile(
        "mma.sync.aligned.m16n8k16.row.col.f32.f16.f16.f32 "
        "{%0,%1,%2,%3}, {%4,%5,%6,%7}, {%8,%9}, {%0,%1,%2,%3};"
        : "+f"(d[0]), "+f"(d[1]), "+f"(d[2]), "+f"(d[3])
        : "r"(a[0]), "r"(a[1]), "r"(a[2]), "r"(a[3]), "r"(b[0]), "r"(b[1]));
}

__device__ __forceinline__ void ldmatrix_x4(uint32_t* r, uint32_t addr){
    asm volatile(
        "ldmatrix.sync.aligned.m8n8.x4.shared.b16 {%0,%1,%2,%3}, [%4];"
        : "=r"(r[0]), "=r"(r[1]), "=r"(r[2]), "=r"(r[3]) : "r"(addr));
}

__device__ __forceinline__ uint32_t smem_u32(const void* p){
    uint32_t a;
    asm("{ .reg .u64 t; cvta.to.shared.u64 t, %1; cvt.u32.u64 %0, t; }"
        : "=r"(a) : "l"(p));
    return a;
}

// ------------------------------- prep kernel -------------------------------
// B layout (u32 within chunk): idx = ((ks*16+nt)*32+lane)*4 + split*2 + reg
__global__ void prep_kernel(const float* __restrict__ w2,
                            const float* __restrict__ cb)
{
    int i = blockIdx.x * blockDim.x + threadIdx.x;
    if (i == 0) g_flagcnt = 0;
    if (i < NBFRAG) {
        int reg   = i & 1;
        int split = (i >> 1) & 1;
        int lane  = (i >> 2) & 31;
        int nt    = (i >> 7) & 15;
        int ks    = (i >> 11) & 1;
        int s     = i >> 12;
        int gr = lane >> 2, gc = lane & 3;
        int l  = nt*8 + gr;
        int tap = s >> 3;
        int c0 = (s & 7)*32 + ks*16 + gc*2 + reg*8;
        float v0 = w2[l*768 + c0*3 + tap];
        float v1 = w2[l*768 + (c0+1)*3 + tap];
        uint32_t lo = (uint32_t)__half_as_ushort(__float2half_rn(fp16_split_val(v0, split)));
        uint32_t hi = (uint32_t)__half_as_ushort(__float2half_rn(fp16_split_val(v1, split)));
        g_Bfrag[i] = lo | (hi << 16);
    } else if (i < NBFRAG + KTOT*LAT) {
        int j = i - NBFRAG;
        int l  = j & 127;
        int kk = j >> 7;
        int c  = kk & 255;
        int k  = kk >> 8;
        g_w2t[j] = w2[l*KTOT + c*3 + k];
    } else {
        int j = i - NBFRAG - KTOT*LAT;
        if (j < NQ*NEMB) {
            const float4* row = (const float4*)(cb + (size_t)j*LAT);
            float s = 0.f;
            #pragma unroll
            for (int m = 0; m < LAT/4; m++) {
                float4 v = row[m];
                s = __fmaf_rn(v.x, v.x, s);
                s = __fmaf_rn(v.y, v.y, s);
                s = __fmaf_rn(v.z, v.z, s);
                s = __fmaf_rn(v.w, v.w, s);
            }
            g_cnorm[j] = s;
        }
    }
}

// ---------- fast encoder (fp16 x3, cc-major, gen-once, ldmatrix) -----------
#define FXS_O   0                 /* 136 floats */
#define FW1_O   136
#define FB1_O   (136+768)
#define FB2_O   (136+768+256)     /* 1160 */
#define R1H_O   1288              /* 132 rows x 40 halves = 2640 floats */
#define R1L_O   (R1H_O + 2640)    /* 3928 */
#define FB_O    (R1L_O + 2640)    /* 6568; 3 x 4096 u32 */
#define FAST_SMEM_FLOATS (FB_O + 3*4096)   /* 18856 -> 75424 B */
#define FAST_SMEM_BYTES  (FAST_SMEM_FLOATS*4)
#define RSH     40                /* r1 row stride in halves (80 B) */

__global__ void __launch_bounds__(256, 2)
encoder_fast(const float* __restrict__ x,  const float* __restrict__ w1,
             const float* __restrict__ b1, const float* __restrict__ b2)
{
    extern __shared__ float sm[];
    char* smc = (char*)sm;
    uint32_t* Bsm = (uint32_t*)(sm + FB_O);
    __half* r1h = (__half*)(smc + R1H_O*4);
    __half* r1l = (__half*)(smc + R1L_O*4);

    const int tid  = threadIdx.x;
    const int lane = tid & 31;
    const int wid  = tid >> 5;
    const int wm   = wid & 3;          // warp rows: wm*32 .. +31
    const int wn   = wid >> 2;         // warp cols: wn*64 .. +63

    const int g  = blockIdx.x;
    const int b  = g / NT;
    const int t0 = (g % NT) * TILE_T;

    // dead 16-row-block skip (warp-uniform): block start t0+wm*32+mi*16
    const int vmi0 = (t0 + wm*32        < FEAT);
    const int vmi1 = (t0 + wm*32 + 16   < FEAT);

    if (tid < 136) {
        int t = t0 - 2 + tid;
        sm[FXS_O + tid] = ((unsigned)t < (unsigned)FEAT)
                        ? x[(size_t)b*FEAT + t] : 0.f;
    }
    for (int i = tid; i < HID*3; i += 256) sm[FW1_O + i] = w1[i];
    if (tid < HID) sm[FB1_O + tid] = b1[tid];
    if (tid < LAT) sm[FB2_O + tid] = b2[tid];

    float acc[2][8][4];
    #pragma unroll
    for (int mi = 0; mi < 2; mi++)
        #pragma unroll
        for (int j = 0; j < 8; j++)
            #pragma unroll
            for (int r = 0; r < 4; r++) acc[mi][j][r] = 0.f;

    // ldmatrix lane mapping
    const int rowit = (lane & 7) + ((lane >> 3) & 1)*8;   // 0..15
    const int chsel = lane >> 4;                          // 0..1
    const uint32_t smbR1H = smem_u32(smc + R1H_O*4);
    const uint32_t smbR1L = smem_u32(smc + R1L_O*4);

    const int rev = blockIdx.x & 1;    // desync co-resident CTA pair

    __syncthreads();

    for (int ccit = 0; ccit < 8; ccit++) {
        const int cc = rev ? (7 - ccit) : ccit;
        __syncthreads();   // buffers free of prior readers

        // ---- stage B for all 3 taps of this cc (48 KB) ----
        #pragma unroll
        for (int tap = 0; tap < 3; tap++) {
            const uint4* src = (const uint4*)(g_Bfrag + (tap*8 + cc)*CHUNK_U32);
            uint4* dst = (uint4*)(Bsm + tap*4096);
            #pragma unroll
            for (int r = 0; r < 4; r++) dst[tid + r*256] = src[tid + r*256];
        }

        // ---- gen r1 ONCE for this cc: rows tt=0..129 (u = t0+tt-1) ----
        {
            const int c   = cc*32 + lane;
            const float wa = sm[FW1_O + c*3 + 0];
            const float wb = sm[FW1_O + c*3 + 1];
            const float wc = sm[FW1_O + c*3 + 2];
            const float bb = sm[FB1_O + c];
            for (int tt = wid; tt < 130; tt += 8) {
                const int u = t0 + tt - 1;
                float v = 0.f;
                if ((unsigned)u < (unsigned)FEAT) {
                    v = __fmul_rn(wa, sm[FXS_O + tt]);
                    v = __fmaf_rn(wb, sm[FXS_O + tt + 1], v);
                    v = __fmaf_rn(wc, sm[FXS_O + tt + 2], v);
                    v = fmaxf(__fadd_rn(v, bb), 0.f);
                }
                __half hh = __float2half_rn(v);
                float  hf = __half2float(hh);
                __half lh = __float2half_rn(v - hf);
                r1h[tt*RSH + lane] = hh;
                r1l[tt*RSH + lane] = lh;
            }
        }
        __syncthreads();

        // ---- 3 taps x 2 ks x 8 j MMA phase (no barriers inside) ----
        #pragma unroll
        for (int tap = 0; tap < 3; tap++) {
            const uint32_t* Bt = Bsm + tap*4096;
            #pragma unroll
            for (int ks = 0; ks < 2; ks++) {
                uint32_t aH[2][4], aL[2][4];
                if (vmi0) {
                    const int tt = wm*32 + rowit + tap;
                    const uint32_t off = (uint32_t)(tt*80 + (ks*2 + chsel)*16);
                    ldmatrix_x4(aH[0], smbR1H + off);
                    ldmatrix_x4(aL[0], smbR1L + off);
                }
                if (vmi1) {
                    const int tt = wm*32 + 16 + rowit + tap;
                    const uint32_t off = (uint32_t)(tt*80 + (ks*2 + chsel)*16);
                    ldmatrix_x4(aH[1], smbR1H + off);
                    ldmatrix_x4(aL[1], smbR1L + off);
                }
                #pragma unroll
                for (int j = 0; j < 8; j++) {
                    const int nt = wn*8 + j;
                    uint4 bq = *(const uint4*)(Bt + ((ks*16 + nt)*32 + lane)*4);
                    uint32_t bH[2] = {bq.x, bq.y};
                    uint32_t bL[2] = {bq.z, bq.w};
                    if (vmi0) {
                        mma_fp16(acc[0][j], aH[0], bH);
                        mma_fp16(acc[0][j], aH[0], bL);
                        mma_fp16(acc[0][j], aL[0], bH);
                    }
                    if (vmi1) {
                        mma_fp16(acc[1][j], aH[1], bH);
                        mma_fp16(acc[1][j], aH[1], bL);
                        mma_fp16(acc[1][j], aL[1], bH);
                    }
                }
            }
        }
    }

    // ---- epilogue: relu(D + b2), fp64 fixed-order t-sum ----
    __syncthreads();
    double* dpart = (double*)(sm + R1H_O);   // r1 region dead

    const int qrow = lane >> 2;
    const int qcol = lane & 3;
    #pragma unroll
    for (int j = 0; j < 8; j++) {
        double s0 = 0.0, s1 = 0.0;
        const int l0 = wn*64 + j*8 + 2*qcol;
        const float bz0 = sm[FB2_O + l0];
        const float bz1 = sm[FB2_O + l0 + 1];
        #pragma unroll
        for (int mi = 0; mi < 2; mi++) {
            const int ra  = t0 + wm*32 + mi*16 + qrow;
            const int rb2 = ra + 8;
            if (ra < FEAT) {
                s0 += (double)fmaxf(__fadd_rn(acc[mi][j][0], bz0), 0.f);
                s1 += (double)fmaxf(__fadd_rn(acc[mi][j][1], bz1), 0.f);
            }
            if (rb2 < FEAT) {
                s0 += (double)fmaxf(__fadd_rn(acc[mi][j][2], bz0), 0.f);
                s1 += (double)fmaxf(__fadd_rn(acc[mi][j][3], bz1), 0.f);
            }
        }
        #pragma unroll
        for (int off = 4; off < 32; off <<= 1) {
            s0 += __shfl_xor_sync(0xffffffffu, s0, off);
            s1 += __shfl_xor_sync(0xffffffffu, s1, off);
        }
        if (qrow == 0) {
            dpart[wm*128 + l0]     = s0;
            dpart[wm*128 + l0 + 1] = s1;
        }
    }
    __syncthreads();
    if (tid < LAT) {
        double z = ((dpart[tid] + dpart[128 + tid]) + dpart[256 + tid]) + dpart[384 + tid];
        g_zpart[(size_t)g*LAT + tid] = z;
    }
}

// --------------------- RVQ core (proven, inlined) ---------------------------
__device__ __forceinline__ void rvq_row(const float* __restrict__ cb,
                                        float* res, float* qs, int* sidx,
                                        int lane, int flag_mode, int b_row)
{
    bool flagged = false;

    for (int q = 0; q < NQ; q++) {
        const float* cbq = cb + (size_t)q*NEMB*LAT;
        const float* cnq = g_cnorm + q*NEMB;

        float A;
        {
            float sA = 0.f;
            #pragma unroll
            for (int m = 0; m < 4; m++) {
                float rv = res[lane + 32*m];
                sA = __fmaf_rn(rv, rv, sA);
            }
            #pragma unroll
            for (int off = 16; off > 0; off >>= 1)
                sA = __fadd_rn(sA, __shfl_xor_sync(0xffffffffu, sA, off));
            A = sA;
        }

        float b1v = CUDART_INF_F, b2v = CUDART_INF_F;
        int   j1  = 0x7fffffff;
        #pragma unroll 1
        for (int jj = 0; jj < NEMB/32; jj++) {
            const int j = (lane << 4) + jj;
            const float4* crow = (const float4*)(cbq + (size_t)j*LAT);
            const float4* rrow = (const float4*)res;
            float dot = 0.f;
            #pragma unroll
            for (int m = 0; m < LAT/4; m++) {
                float4 cv = crow[m];
                float4 rv = rrow[m];
                dot = __fmaf_rn(cv.x, rv.x, dot);
                dot = __fmaf_rn(cv.y, rv.y, dot);
                dot = __fmaf_rn(cv.z, rv.z, dot);
                dot = __fmaf_rn(cv.w, rv.w, dot);
            }
            float t1 = __fmaf_rn(-2.f, dot, A);
            float d  = __fadd_rn(t1, cnq[j]);
            if (d < b1v) { b2v = b1v; b1v = d; j1 = j; }
            else if (d < b2v) { b2v = d; }
        }
        #pragma unroll
        for (int off = 16; off > 0; off >>= 1) {
            float ob1 = __shfl_xor_sync(0xffffffffu, b1v, off);
            int   oj1 = __shfl_xor_sync(0xffffffffu, j1,  off);
            float ob2 = __shfl_xor_sync(0xffffffffu, b2v, off);
            if (ob1 < b1v || (ob1 == b1v && oj1 < j1)) {
                b2v = fminf(b1v, ob2);
                b1v = ob1; j1 = oj1;
            } else {
                b2v = fminf(b2v, ob1);
            }
        }
        if (flag_mode && (b2v - b1v) < MARGIN) flagged = true;
        if (lane == 0) sidx[q] = j1;

        #pragma unroll
        for (int m = 0; m < 4; m++) {
            int d = lane + 32*m;
            float c = cbq[(size_t)j1*LAT + d];
            res[d] = __fadd_rn(res[d], -c);
            qs[m] = __fadd_rn(qs[m], c);
        }
        __syncwarp();
    }

    if (flag_mode && flagged && lane == 0) {
        int pos = atomicAdd(&g_flagcnt, 1);
        g_flaglist[pos] = b_row;
    }
}

// ------------- RVQ pass 1: fused z-reduce (fp64) + RVQ + flags --------------
__global__ void __launch_bounds__(256)
rvq_flag(const float* __restrict__ cb,
         float* __restrict__ out_zq, float* __restrict__ out_idx,
         int write_zq, int write_idx)
{
    __shared__ __align__(16) float res[8][LAT];
    __shared__ int sidx[8][NQ];

    const int tid  = threadIdx.x;
    const int w    = tid >> 5;
    const int lane = tid & 31;
    const int b    = blockIdx.x * 8 + w;

    float qs[4] = {0.f, 0.f, 0.f, 0.f};
    #pragma unroll
    for (int m = 0; m < 4; m++) {
        const int d = lane + 32*m;
        double s = 0.0;
        #pragma unroll
        for (int t = 0; t < NT; t++)
            s += g_zpart[(size_t)(b*NT + t)*LAT + d];
        res[w][d] = __fdiv_rn((float)s, (float)FEAT);
    }
    __syncwarp();

    rvq_row(cb, res[w], qs, sidx[w], lane, 1, b);

    if (write_zq) {
        #pragma unroll
        for (int m = 0; m < 4; m++)
            out_zq[(size_t)b*LAT + lane + 32*m] = qs[m];
    }
    if (write_idx && lane < NQ)
        out_idx[(size_t)b*NQ + lane] = (float)sidx[w][lane];
}

// -------------------- exact encoder chunk (bit-exact chain) -----------------
#define TCX   128
#define CG    64
#define RSP   132
#define EXS_O   0
#define EW1_O   844
#define EB1_O   (844+768)
#define ER1_O   (844+768+256)
#define EW2T_O  (ER1_O + CG*RSP*2)
#define EX_SMEM_FLOATS (EW2T_O + CG*LAT)
#define EX_SMEM_BYTES  (EX_SMEM_FLOATS*4)

__device__ __forceinline__ ull ffma2(ull a, ull b, ull c){
    ull d;
    asm("fma.rn.f32x2 %0, %1, %2, %3;" : "=l"(d) : "l"(a), "l"(b), "l"(c));
    return d;
}
__device__ __forceinline__ float2 unpack2(ull v){
    float2 f; asm("mov.b64 {%0,%1}, %2;" : "=f"(f.x), "=f"(f.y) : "l"(v));
    return f;
}
__device__ __forceinline__ ull splat2(float v){
    ull d; asm("mov.b64 %0, {%1,%1};" : "=l"(d) : "f"(v));
    return d;
}

__global__ void __launch_bounds__(256, 2)
exact_chunk(const float* __restrict__ x,  const float* __restrict__ w1,
            const float* __restrict__ b1, const float* __restrict__ b2)
{
    const int cnt = g_flagcnt;
    const int i   = blockIdx.x;
    if (i >= cnt * NT) return;
    const int b  = g_flaglist[i / NT];
    const int ch = i % NT;

    extern __shared__ float sm[];
    float* xs  = sm + EXS_O;
    float* w1s = sm + EW1_O;
    float* b1s = sm + EB1_O;
    ull*   r1s2 = (ull*)(sm + ER1_O);
    const ulonglong2* wt = (const ulonglong2*)(sm + EW2T_O);

    const int tid  = threadIdx.x;
    const int lane = tid & 31;
    const int w8   = tid >> 5;
    const int l0   = lane * 4;
    const int gcc  = tid >> 2;
    const int gsub = tid & 3;

    for (int ii = tid; ii < FEAT; ii += 256) xs[ii + 1] = x[(size_t)b*FEAT + ii];
    for (int ii = tid; ii < HID*3; ii += 256) w1s[ii] = w1[ii];
    if (tid < HID) b1s[tid] = b1[tid];
    if (tid == 0) { xs[0] = 0.f; xs[FEAT + 1] = 0.f; xs[FEAT + 2] = 0.f; }

    float bl[4];
    #pragma unroll
    for (int j = 0; j < 4; j++) bl[j] = b2[l0 + j];

    double zp[4] = {0.0, 0.0, 0.0, 0.0};
    __syncthreads();

    const int t0 = ch * TCX;

    ull acc[2][16];
    #pragma unroll
    for (int p = 0; p < 2; p++)
        #pragma unroll
        for (int ii = 0; ii < 16; ii++) acc[p][ii] = 0ull;

    for (int g = 0; g < 4; g++) {
        __syncthreads();
        {
            const int c  = g*CG + gcc;
            const float wa = w1s[c*3+0], wb = w1s[c*3+1], wc = w1s[c*3+2];
            const float bb1 = b1s[c];
            #pragma unroll
            for (int s = 0; s < 33; s++) {
                int tt = gsub + 4*s;
                if (tt < TCX + 2) {
                    int t = t0 - 1 + tt;
                    float v = 0.f;
                    if ((unsigned)t < (unsigned)FEAT) {
                        v = __fmul_rn(wa, xs[t]);
                        v = __fmaf_rn(wb, xs[t+1], v);
                        v = __fmaf_rn(wc, xs[t+2], v);
                        v = fmaxf(__fadd_rn(v, bb1), 0.f);
                    }
                    r1s2[gcc*RSP + tt] = splat2(v);
                }
            }
        }

        #pragma unroll
        for (int k = 0; k < 3; k++) {
            __syncthreads();
            {
                const float4* src = (const float4*)(g_w2t + (size_t)(k*HID + g*CG)*LAT);
                float4* dst = (float4*)(sm + EW2T_O);
                #pragma unroll
                for (int r = 0; r < 8; r++) dst[tid + r*256] = src[tid + r*256];
            }
            __syncthreads();

            #pragma unroll 2
            for (int kk = 0; kk < CG; kk++) {
                ulonglong2 a2 = wt[kk*32 + lane];
                const ulonglong2* brow =
                    (const ulonglong2*)(r1s2 + kk*RSP) + w8*8;
                #pragma unroll
                for (int j = 0; j < 9; j++) {
                    ulonglong2 bb = brow[j];
                    const int i0 = 2*j - k;
                    const int i1 = 2*j + 1 - k;
                    if (i0 >= 0 && i0 < 16) {
                        acc[0][i0] = ffma2(a2.x, bb.x, acc[0][i0]);
                        acc[1][i0] = ffma2(a2.y, bb.x, acc[1][i0]);
                    }
                    if (i1 >= 0 && i1 < 16) {
                        acc[0][i1] = ffma2(a2.x, bb.y, acc[0][i1]);
                        acc[1][i1] = ffma2(a2.y, bb.y, acc[1][i1]);
                    }
                }
            }
        }
    }

    #pragma unroll
    for (int ii = 0; ii < 16; ii++) {
        if (t0 + w8*16 + ii < FEAT) {
            #pragma unroll
            for (int p = 0; p < 2; p++) {
                float2 f = unpack2(acc[p][ii]);
                zp[2*p+0] += (double)fmaxf(__fadd_rn(f.x, bl[2*p+0]), 0.f);
                zp[2*p+1] += (double)fmaxf(__fadd_rn(f.y, bl[2*p+1]), 0.f);
            }
        }
    }

    __syncthreads();
    double* dp = (double*)(sm + ER1_O);
    #pragma unroll
    for (int j = 0; j < 4; j++) dp[w8*128 + l0 + j] = zp[j];
    __syncthreads();
    if (tid < LAT) {
        double v = dp[tid];
        #pragma unroll
        for (int w = 1; w < 8; w++) v += dp[w*128 + tid];
        g_zpart[(size_t)(b*NT + ch)*LAT + tid] = v;
    }
}

// --------------------- fixed rows: reduce + RVQ redo ------------------------
__global__ void fix_reduce()
{
    int idx = blockIdx.x * blockDim.x + threadIdx.x;
    int p = idx >> 7;
    if (p >= g_flagcnt) return;
    int b = g_flaglist[p];
    int l = idx & 127;
    double s = 0.0;
    #pragma unroll
    for (int t = 0; t < NT; t++)
        s += g_zpart[(size_t)(b*NT + t)*LAT + l];
    g_z[(size_t)b*LAT + l] = __fdiv_rn((float)s, (float)FEAT);
}

__global__ void __launch_bounds__(256)
rvq_fix(const float* __restrict__ cb,
        float* __restrict__ out_zq, float* __restrict__ out_idx,
        int write_zq, int write_idx)
{
    __shared__ __align__(16) float res[8][LAT];
    __shared__ int sidx[8][NQ];

    const int tid  = threadIdx.x;
    const int w    = tid >> 5;
    const int lane = tid & 31;
    const int slot = blockIdx.x * 8 + w;
    if (slot >= g_flagcnt) return;
    const int b = g_flaglist[slot];

    float qs[4] = {0.f, 0.f, 0.f, 0.f};
    #pragma unroll
    for (int m = 0; m < 4; m++)
        res[w][lane + 32*m] = g_z[(size_t)b*LAT + lane + 32*m];
    __syncwarp();

    rvq_row(cb, res[w], qs, sidx[w], lane, 0, b);

    if (write_zq) {
        #pragma unroll
        for (int m = 0; m < 4; m++)
            out_zq[(size_t)b*LAT + lane + 32*m] = qs[m];
    }
    if (write_idx && lane < NQ)
        out_idx[(size_t)b*NQ + lane] = (float)sidx[w][lane];
}

// ---------------------------------------------------------------------------
extern "C" void kernel_launch(void* const* d_in, const int* in_sizes, int n_in,
                              void* d_out, int out_size)
{
    const float* x  = (const float*)d_in[0];
    const float* w1 = (const float*)d_in[1];
    const float* b1 = (const float*)d_in[2];
    const float* w2 = (const float*)d_in[3];
    const float* b2 = (const float*)d_in[4];
    const float* cb = (const float*)d_in[5];

    cudaFuncSetAttribute(encoder_fast,
                         cudaFuncAttributeMaxDynamicSharedMemorySize,
                         FAST_SMEM_BYTES);
    cudaFuncSetAttribute(exact_chunk,
                         cudaFuncAttributeMaxDynamicSharedMemorySize,
                         EX_SMEM_BYTES);

    float* out_zq  = (float*)d_out;
    float* out_idx = (float*)d_out + (size_t)B_SZ*LAT;
    int write_zq = 1, write_idx = 1;
    if (out_size >= B_SZ*(LAT + NQ)) {
    } else if (out_size >= B_SZ*LAT) {
        write_idx = 0;
    } else {
        write_zq = 0;
        out_idx  = (float*)d_out;
    }

    const int total = NBFRAG + KTOT*LAT + NQ*NEMB;
    prep_kernel<<<(total + 255)/256, 256>>>(w2, cb);
    encoder_fast<<<TILES_TOT, 256, FAST_SMEM_BYTES>>>(x, w1, b1, b2);
    rvq_flag<<<B_SZ/8, 256>>>(cb, out_zq, out_idx, write_zq, write_idx);
    exact_chunk<<<TILES_TOT, 256, EX_SMEM_BYTES>>>(x, w1, b1, b2);
    fix_reduce<<<(B_SZ*LAT + 255)/256, 256>>>();
    rvq_fix<<<B_SZ/8, 256>>>(cb, out_zq, out_idx, write_zq, write_idx);
}

// round 15
// speedup vs baseline: 1.1183x; 1.1183x over previous
#include <cuda_runtime.h>
#include <cuda_fp16.h>
#include <math_constants.h>
#include <cstdint>

#define B_SZ  2048
#define FEAT  840
#define HID   256
#define LAT   128
#define NQ    12
#define NEMB  512
#define KTOT  768

#define NT        7
#define TILE_T    128
#define TILES_TOT (B_SZ*NT)           /* 14336 */
#define NCHK      24
#define CHUNK_U32 4096                /* B frag words per chunk */
#define NBFRAG    (NCHK*CHUNK_U32)    /* 98304 */

#define MARGIN 1e-6f

typedef unsigned long long ull;

// ----------------------------- device scratch ------------------------------
__device__ __align__(16) uint32_t g_Bfrag[NBFRAG];   // w2 fp16 2-split frags
__device__ __align__(16) float g_w2t[KTOT*LAT];      // exact path [(k*256+c)][l]
__device__ float  g_cnorm[NQ*NEMB];
__device__ double g_zpart[(size_t)TILES_TOT*LAT];
__device__ __align__(16) float g_z[B_SZ*LAT];
__device__ int g_flagcnt;
__device__ int g_flaglist[B_SZ];

__device__ __forceinline__ float fp16_split_val(float v, int split){
    float h = __half2float(__float2half_rn(v));
    if (split == 0) return h;
    return v - h;
}

__device__ __forceinline__ void mma_fp16(float* d, const uint32_t* a, const uint32_t* b){
    asm volatile(
        "mma.sync.aligned.m16n8k16.row.col.f32.f16.f16.f32 "
        "{%0,%1,%2,%3}, {%4,%5,%6,%7}, {%8,%9}, {%0,%1,%2,%3};"
        : "+f"(d[0]), "+f"(d[1]), "+f"(d[2]), "+f"(d[3])
        : "r"(a[0]), "r"(a[1]), "r"(a[2]), "r"(a[3]), "r"(b[0]), "r"(b[1]));
}

__device__ __forceinline__ void ldmatrix_x4(uint32_t* r, uint32_t addr){
    asm volatile(
        "ldmatrix.sync.aligned.m8n8.x4.shared.b16 {%0,%1,%2,%3}, [%4];"
        : "=r"(r[0]), "=r"(r[1]), "=r"(r[2]), "=r"(r[3]) : "r"(addr));
}

__device__ __forceinline__ uint32_t smem_u32(const void* p){
    uint32_t a;
    asm("{ .reg .u64 t; cvta.to.shared.u64 t, %1; cvt.u32.u64 %0, t; }"
        : "=r"(a) : "l"(p));
    return a;
}

// ------------------------------- prep kernel -------------------------------
// B layout (u32 within chunk): idx = ((ks*16+nt)*32+lane)*4 + split*2 + reg
__global__ void prep_kernel(const float* __restrict__ w2,
                            const float* __restrict__ cb)
{
    int i = blockIdx.x * blockDim.x + threadIdx.x;
    if (i == 0) g_flagcnt = 0;
    if (i < NBFRAG) {
        int reg   = i & 1;
        int split = (i >> 1) & 1;
        int lane  = (i >> 2) & 31;
        int nt    = (i >> 7) & 15;
        int ks    = (i >> 11) & 1;
        int s     = i >> 12;
        int gr = lane >> 2, gc = lane & 3;
        int l  = nt*8 + gr;
        int tap = s >> 3;
        int c0 = (s & 7)*32 + ks*16 + gc*2 + reg*8;
        float v0 = w2[l*768 + c0*3 + tap];
        float v1 = w2[l*768 + (c0+1)*3 + tap];
        uint32_t lo = (uint32_t)__half_as_ushort(__float2half_rn(fp16_split_val(v0, split)));
        uint32_t hi = (uint32_t)__half_as_ushort(__float2half_rn(fp16_split_val(v1, split)));
        g_Bfrag[i] = lo | (hi << 16);
    } else if (i < NBFRAG + KTOT*LAT) {
        int j = i - NBFRAG;
        int l  = j & 127;
        int kk = j >> 7;
        int c  = kk & 255;
        int k  = kk >> 8;
        g_w2t[j] = w2[l*KTOT + c*3 + k];
    } else {
        int j = i - NBFRAG - KTOT*LAT;
        if (j < NQ*NEMB) {
            const float4* row = (const float4*)(cb + (size_t)j*LAT);
            float s = 0.f;
            #pragma unroll
            for (int m = 0; m < LAT/4; m++) {
                float4 v = row[m];
                s = __fmaf_rn(v.x, v.x, s);
                s = __fmaf_rn(v.y, v.y, s);
                s = __fmaf_rn(v.z, v.z, s);
                s = __fmaf_rn(v.w, v.w, s);
            }
            g_cnorm[j] = s;
        }
    }
}

// ---------- fast encoder (fp16 x3, cc-major, gen-once, ldmatrix) -----------
// (byte-identical to the 5537us R13 kernel)
#define FXS_O   0                 /* 136 floats */
#define FW1_O   136
#define FB1_O   (136+768)
#define FB2_O   (136+768+256)     /* 1160 */
#define R1H_O   1288              /* 132 rows x 40 halves = 2640 floats */
#define R1L_O   (R1H_O + 2640)    /* 3928 */
#define FB_O    (R1L_O + 2640)    /* 6568; 3 x 4096 u32 */
#define FAST_SMEM_FLOATS (FB_O + 3*4096)   /* 18856 -> 75424 B */
#define FAST_SMEM_BYTES  (FAST_SMEM_FLOATS*4)
#define RSH     40                /* r1 row stride in halves (80 B) */

__global__ void __launch_bounds__(256, 2)
encoder_fast(const float* __restrict__ x,  const float* __restrict__ w1,
             const float* __restrict__ b1, const float* __restrict__ b2)
{
    extern __shared__ float sm[];
    char* smc = (char*)sm;
    uint32_t* Bsm = (uint32_t*)(sm + FB_O);
    __half* r1h = (__half*)(smc + R1H_O*4);
    __half* r1l = (__half*)(smc + R1L_O*4);

    const int tid  = threadIdx.x;
    const int lane = tid & 31;
    const int wid  = tid >> 5;
    const int wm   = wid & 3;          // warp rows: wm*32 .. +31
    const int wn   = wid >> 2;         // warp cols: wn*64 .. +63

    const int g  = blockIdx.x;
    const int b  = g / NT;
    const int t0 = (g % NT) * TILE_T;

    if (tid < 136) {
        int t = t0 - 2 + tid;
        sm[FXS_O + tid] = ((unsigned)t < (unsigned)FEAT)
                        ? x[(size_t)b*FEAT + t] : 0.f;
    }
    for (int i = tid; i < HID*3; i += 256) sm[FW1_O + i] = w1[i];
    if (tid < HID) sm[FB1_O + tid] = b1[tid];
    if (tid < LAT) sm[FB2_O + tid] = b2[tid];

    float acc[2][8][4];
    #pragma unroll
    for (int mi = 0; mi < 2; mi++)
        #pragma unroll
        for (int j = 0; j < 8; j++)
            #pragma unroll
            for (int r = 0; r < 4; r++) acc[mi][j][r] = 0.f;

    // ldmatrix lane mapping
    const int rowit = (lane & 7) + ((lane >> 3) & 1)*8;   // 0..15
    const int chsel = lane >> 4;                          // 0..1
    const uint32_t smbR1H = smem_u32(smc + R1H_O*4);
    const uint32_t smbR1L = smem_u32(smc + R1L_O*4);

    __syncthreads();

    for (int cc = 0; cc < 8; cc++) {
        __syncthreads();   // buffers free of prior readers

        // ---- stage B for all 3 taps of this cc (48 KB) ----
        #pragma unroll
        for (int tap = 0; tap < 3; tap++) {
            const uint4* src = (const uint4*)(g_Bfrag + (tap*8 + cc)*CHUNK_U32);
            uint4* dst = (uint4*)(Bsm + tap*4096);
            #pragma unroll
            for (int r = 0; r < 4; r++) dst[tid + r*256] = src[tid + r*256];
        }

        // ---- gen r1 ONCE for this cc: rows tt=0..129 (u = t0+tt-1) ----
        {
            const int c   = cc*32 + lane;
            const float wa = sm[FW1_O + c*3 + 0];
            const float wb = sm[FW1_O + c*3 + 1];
            const float wc = sm[FW1_O + c*3 + 2];
            const float bb = sm[FB1_O + c];
            for (int tt = wid; tt < 130; tt += 8) {
                const int u = t0 + tt - 1;
                float v = 0.f;
                if ((unsigned)u < (unsigned)FEAT) {
                    v = __fmul_rn(wa, sm[FXS_O + tt]);
                    v = __fmaf_rn(wb, sm[FXS_O + tt + 1], v);
                    v = __fmaf_rn(wc, sm[FXS_O + tt + 2], v);
                    v = fmaxf(__fadd_rn(v, bb), 0.f);
                }
                __half hh = __float2half_rn(v);
                float  hf = __half2float(hh);
                __half lh = __float2half_rn(v - hf);
                r1h[tt*RSH + lane] = hh;
                r1l[tt*RSH + lane] = lh;
            }
        }
        __syncthreads();

        // ---- 3 taps x 2 ks x 8 j MMA phase (no barriers inside) ----
        #pragma unroll
        for (int tap = 0; tap < 3; tap++) {
            const uint32_t* Bt = Bsm + tap*4096;
            #pragma unroll
            for (int ks = 0; ks < 2; ks++) {
                uint32_t aH[2][4], aL[2][4];
                #pragma unroll
                for (int mi = 0; mi < 2; mi++) {
                    const int tt = wm*32 + mi*16 + rowit + tap;
                    const uint32_t off = (uint32_t)(tt*80 + (ks*2 + chsel)*16);
                    ldmatrix_x4(aH[mi], smbR1H + off);
                    ldmatrix_x4(aL[mi], smbR1L + off);
                }
                #pragma unroll
                for (int j = 0; j < 8; j++) {
                    const int nt = wn*8 + j;
                    uint4 bq = *(const uint4*)(Bt + ((ks*16 + nt)*32 + lane)*4);
                    uint32_t bH[2] = {bq.x, bq.y};
                    uint32_t bL[2] = {bq.z, bq.w};
                    #pragma unroll
                    for (int mi = 0; mi < 2; mi++) {
                        mma_fp16(acc[mi][j], aH[mi], bH);   // hh
                        mma_fp16(acc[mi][j], aH[mi], bL);   // hl
                        mma_fp16(acc[mi][j], aL[mi], bH);   // lh
                    }
                }
            }
        }
    }

    // ---- epilogue: relu(D + b2), fp64 fixed-order t-sum ----
    __syncthreads();
    double* dpart = (double*)(sm + R1H_O);   // r1 region dead

    const int qrow = lane >> 2;
    const int qcol = lane & 3;
    #pragma unroll
    for (int j = 0; j < 8; j++) {
        double s0 = 0.0, s1 = 0.0;
        const int l0 = wn*64 + j*8 + 2*qcol;
        const float bz0 = sm[FB2_O + l0];
        const float bz1 = sm[FB2_O + l0 + 1];
        #pragma unroll
        for (int mi = 0; mi < 2; mi++) {
            const int ra  = t0 + wm*32 + mi*16 + qrow;
            const int rb2 = ra + 8;
            if (ra < FEAT) {
                s0 += (double)fmaxf(__fadd_rn(acc[mi][j][0], bz0), 0.f);
                s1 += (double)fmaxf(__fadd_rn(acc[mi][j][1], bz1), 0.f);
            }
            if (rb2 < FEAT) {
                s0 += (double)fmaxf(__fadd_rn(acc[mi][j][2], bz0), 0.f);
                s1 += (double)fmaxf(__fadd_rn(acc[mi][j][3], bz1), 0.f);
            }
        }
        #pragma unroll
        for (int off = 4; off < 32; off <<= 1) {
            s0 += __shfl_xor_sync(0xffffffffu, s0, off);
            s1 += __shfl_xor_sync(0xffffffffu, s1, off);
        }
        if (qrow == 0) {
            dpart[wm*128 + l0]     = s0;
            dpart[wm*128 + l0 + 1] = s1;
        }
    }
    __syncthreads();
    if (tid < LAT) {
        double z = ((dpart[tid] + dpart[128 + tid]) + dpart[256 + tid]) + dpart[384 + tid];
        g_zpart[(size_t)g*LAT + tid] = z;
    }
}

// --------------------- RVQ core (proven, inlined) ---------------------------
__device__ __forceinline__ void rvq_row(const float* __restrict__ cb,
                                        float* res, float* qs, int* sidx,
                                        int lane, int flag_mode, int b_row)
{
    bool flagged = false;

    for (int q = 0; q < NQ; q++) {
        const float* cbq = cb + (size_t)q*NEMB*LAT;
        const float* cnq = g_cnorm + q*NEMB;

        float A;
        {
            float sA = 0.f;
            #pragma unroll
            for (int m = 0; m < 4; m++) {
                float rv = res[lane + 32*m];
                sA = __fmaf_rn(rv, rv, sA);
            }
            #pragma unroll
            for (int off = 16; off > 0; off >>= 1)
                sA = __fadd_rn(sA, __shfl_xor_sync(0xffffffffu, sA, off));
            A = sA;
        }

        float b1v = CUDART_INF_F, b2v = CUDART_INF_F;
        int   j1  = 0x7fffffff;
        #pragma unroll 1
        for (int jj = 0; jj < NEMB/32; jj++) {
            const int j = (lane << 4) + jj;
            const float4* crow = (const float4*)(cbq + (size_t)j*LAT);
            const float4* rrow = (const float4*)res;
            float dot = 0.f;
            #pragma unroll
            for (int m = 0; m < LAT/4; m++) {
                float4 cv = crow[m];
                float4 rv = rrow[m];
                dot = __fmaf_rn(cv.x, rv.x, dot);
                dot = __fmaf_rn(cv.y, rv.y, dot);
                dot = __fmaf_rn(cv.z, rv.z, dot);
                dot = __fmaf_rn(cv.w, rv.w, dot);
            }
            float t1 = __fmaf_rn(-2.f, dot, A);
            float d  = __fadd_rn(t1, cnq[j]);
            if (d < b1v) { b2v = b1v; b1v = d; j1 = j; }
            else if (d < b2v) { b2v = d; }
        }
        #pragma unroll
        for (int off = 16; off > 0; off >>= 1) {
            float ob1 = __shfl_xor_sync(0xffffffffu, b1v, off);
            int   oj1 = __shfl_xor_sync(0xffffffffu, j1,  off);
            float ob2 = __shfl_xor_sync(0xffffffffu, b2v, off);
            if (ob1 < b1v || (ob1 == b1v && oj1 < j1)) {
                b2v = fminf(b1v, ob2);
                b1v = ob1; j1 = oj1;
            } else {
                b2v = fminf(b2v, ob1);
            }
        }
        if (flag_mode && (b2v - b1v) < MARGIN) flagged = true;
        if (lane == 0) sidx[q] = j1;

        #pragma unroll
        for (int m = 0; m < 4; m++) {
            int d = lane + 32*m;
            float c = cbq[(size_t)j1*LAT + d];
            res[d] = __fadd_rn(res[d], -c);
            qs[m] = __fadd_rn(qs[m], c);
        }
        __syncwarp();
    }

    if (flag_mode && flagged && lane == 0) {
        int pos = atomicAdd(&g_flagcnt, 1);
        g_flaglist[pos] = b_row;
    }
}

// ------------- RVQ pass 1: fused z-reduce (fp64) + RVQ + flags --------------
__global__ void __launch_bounds__(256)
rvq_flag(const float* __restrict__ cb,
         float* __restrict__ out_zq, float* __restrict__ out_idx,
         int write_zq, int write_idx)
{
    __shared__ __align__(16) float res[8][LAT];
    __shared__ int sidx[8][NQ];

    const int tid  = threadIdx.x;
    const int w    = tid >> 5;
    const int lane = tid & 31;
    const int b    = blockIdx.x * 8 + w;

    float qs[4] = {0.f, 0.f, 0.f, 0.f};
    #pragma unroll
    for (int m = 0; m < 4; m++) {
        const int d = lane + 32*m;
        double s = 0.0;
        #pragma unroll
        for (int t = 0; t < NT; t++)
            s += g_zpart[(size_t)(b*NT + t)*LAT + d];
        res[w][d] = __fdiv_rn((float)s, (float)FEAT);
    }
    __syncwarp();

    rvq_row(cb, res[w], qs, sidx[w], lane, 1, b);

    if (write_zq) {
        #pragma unroll
        for (int m = 0; m < 4; m++)
            out_zq[(size_t)b*LAT + lane + 32*m] = qs[m];
    }
    if (write_idx && lane < NQ)
        out_idx[(size_t)b*NQ + lane] = (float)sidx[w][lane];
}

// -------------------- exact encoder chunk (bit-exact chain) -----------------
#define TCX   128
#define CG    64
#define RSP   132
#define EXS_O   0
#define EW1_O   844
#define EB1_O   (844+768)
#define ER1_O   (844+768+256)
#define EW2T_O  (ER1_O + CG*RSP*2)
#define EX_SMEM_FLOATS (EW2T_O + CG*LAT)
#define EX_SMEM_BYTES  (EX_SMEM_FLOATS*4)

__device__ __forceinline__ ull ffma2(ull a, ull b, ull c){
    ull d;
    asm("fma.rn.f32x2 %0, %1, %2, %3;" : "=l"(d) : "l"(a), "l"(b), "l"(c));
    return d;
}
__device__ __forceinline__ float2 unpack2(ull v){
    float2 f; asm("mov.b64 {%0,%1}, %2;" : "=f"(f.x), "=f"(f.y) : "l"(v));
    return f;
}
__device__ __forceinline__ ull splat2(float v){
    ull d; asm("mov.b64 %0, {%1,%1};" : "=l"(d) : "f"(v));
    return d;
}

__global__ void __launch_bounds__(256, 2)
exact_chunk(const float* __restrict__ x,  const float* __restrict__ w1,
            const float* __restrict__ b1, const float* __restrict__ b2)
{
    const int cnt = g_flagcnt;
    const int i   = blockIdx.x;
    if (i >= cnt * NT) return;
    const int b  = g_flaglist[i / NT];
    const int ch = i % NT;

    extern __shared__ float sm[];
    float* xs  = sm + EXS_O;
    float* w1s = sm + EW1_O;
    float* b1s = sm + EB1_O;
    ull*   r1s2 = (ull*)(sm + ER1_O);
    const ulonglong2* wt = (const ulonglong2*)(sm + EW2T_O);

    const int tid  = threadIdx.x;
    const int lane = tid & 31;
    const int w8   = tid >> 5;
    const int l0   = lane * 4;
    const int gcc  = tid >> 2;
    const int gsub = tid & 3;

    for (int ii = tid; ii < FEAT; ii += 256) xs[ii + 1] = x[(size_t)b*FEAT + ii];
    for (int ii = tid; ii < HID*3; ii += 256) w1s[ii] = w1[ii];
    if (tid < HID) b1s[tid] = b1[tid];
    if (tid == 0) { xs[0] = 0.f; xs[FEAT + 1] = 0.f; xs[FEAT + 2] = 0.f; }

    float bl[4];
    #pragma unroll
    for (int j = 0; j < 4; j++) bl[j] = b2[l0 + j];

    double zp[4] = {0.0, 0.0, 0.0, 0.0};
    __syncthreads();

    const int t0 = ch * TCX;

    ull acc[2][16];
    #pragma unroll
    for (int p = 0; p < 2; p++)
        #pragma unroll
        for (int ii = 0; ii < 16; ii++) acc[p][ii] = 0ull;

    for (int g = 0; g < 4; g++) {
        __syncthreads();
        {
            const int c  = g*CG + gcc;
            const float wa = w1s[c*3+0], wb = w1s[c*3+1], wc = w1s[c*3+2];
            const float bb1 = b1s[c];
            #pragma unroll
            for (int s = 0; s < 33; s++) {
                int tt = gsub + 4*s;
                if (tt < TCX + 2) {
                    int t = t0 - 1 + tt;
                    float v = 0.f;
                    if ((unsigned)t < (unsigned)FEAT) {
                        v = __fmul_rn(wa, xs[t]);
                        v = __fmaf_rn(wb, xs[t+1], v);
                        v = __fmaf_rn(wc, xs[t+2], v);
                        v = fmaxf(__fadd_rn(v, bb1), 0.f);
                    }
                    r1s2[gcc*RSP + tt] = splat2(v);
                }
            }
        }

        #pragma unroll
        for (int k = 0; k < 3; k++) {
            __syncthreads();
            {
                const float4* src = (const float4*)(g_w2t + (size_t)(k*HID + g*CG)*LAT);
                float4* dst = (float4*)(sm + EW2T_O);
                #pragma unroll
                for (int r = 0; r < 8; r++) dst[tid + r*256] = src[tid + r*256];
            }
            __syncthreads();

            #pragma unroll 2
            for (int kk = 0; kk < CG; kk++) {
                ulonglong2 a2 = wt[kk*32 + lane];
                const ulonglong2* brow =
                    (const ulonglong2*)(r1s2 + kk*RSP) + w8*8;
                #pragma unroll
                for (int j = 0; j < 9; j++) {
                    ulonglong2 bb = brow[j];
                    const int i0 = 2*j - k;
                    const int i1 = 2*j + 1 - k;
                    if (i0 >= 0 && i0 < 16) {
                        acc[0][i0] = ffma2(a2.x, bb.x, acc[0][i0]);
                        acc[1][i0] = ffma2(a2.y, bb.x, acc[1][i0]);
                    }
                    if (i1 >= 0 && i1 < 16) {
                        acc[0][i1] = ffma2(a2.x, bb.y, acc[0][i1]);
                        acc[1][i1] = ffma2(a2.y, bb.y, acc[1][i1]);
                    }
                }
            }
        }
    }

    #pragma unroll
    for (int ii = 0; ii < 16; ii++) {
        if (t0 + w8*16 + ii < FEAT) {
            #pragma unroll
            for (int p = 0; p < 2; p++) {
                float2 f = unpack2(acc[p][ii]);
                zp[2*p+0] += (double)fmaxf(__fadd_rn(f.x, bl[2*p+0]), 0.f);
                zp[2*p+1] += (double)fmaxf(__fadd_rn(f.y, bl[2*p+1]), 0.f);
            }
        }
    }

    __syncthreads();
    double* dp = (double*)(sm + ER1_O);
    #pragma unroll
    for (int j = 0; j < 4; j++) dp[w8*128 + l0 + j] = zp[j];
    __syncthreads();
    if (tid < LAT) {
        double v = dp[tid];
        #pragma unroll
        for (int w = 1; w < 8; w++) v += dp[w*128 + tid];
        g_zpart[(size_t)(b*NT + ch)*LAT + tid] = v;
    }
}

// --------------------- fixed rows: reduce + RVQ redo ------------------------
__global__ void fix_reduce()
{
    int idx = blockIdx.x * blockDim.x + threadIdx.x;
    int p = idx >> 7;
    if (p >= g_flagcnt) return;
    int b = g_flaglist[p];
    int l = idx & 127;
    double s = 0.0;
    #pragma unroll
    for (int t = 0; t < NT; t++)
        s += g_zpart[(size_t)(b*NT + t)*LAT + l];
    g_z[(size_t)b*LAT + l] = __fdiv_rn((float)s, (float)FEAT);
}

__global__ void __launch_bounds__(256)
rvq_fix(const float* __restrict__ cb,
        float* __restrict__ out_zq, float* __restrict__ out_idx,
        int write_zq, int write_idx)
{
    __shared__ __align__(16) float res[8][LAT];
    __shared__ int sidx[8][NQ];

    const int tid  = threadIdx.x;
    const int w    = tid >> 5;
    const int lane = tid & 31;
    const int slot = blockIdx.x * 8 + w;
    if (slot >= g_flagcnt) return;
    const int b = g_flaglist[slot];

    float qs[4] = {0.f, 0.f, 0.f, 0.f};
    #pragma unroll
    for (int m = 0; m < 4; m++)
        res[w][lane + 32*m] = g_z[(size_t)b*LAT + lane + 32*m];
    __syncwarp();

    rvq_row(cb, res[w], qs, sidx[w], lane, 0, b);

    if (write_zq) {
        #pragma unroll
        for (int m = 0; m < 4; m++)
            out_zq[(size_t)b*LAT + lane + 32*m] = qs[m];
    }
    if (write_idx && lane < NQ)
        out_idx[(size_t)b*NQ + lane] = (float)sidx[w][lane];
}

// ---------------------------------------------------------------------------
extern "C" void kernel_launch(void* const* d_in, const int* in_sizes, int n_in,
                              void* d_out, int out_size)
{
    const float* x  = (const float*)d_in[0];
    const float* w1 = (const float*)d_in[1];
    const float* b1 = (const float*)d_in[2];
    const float* w2 = (const float*)d_in[3];
    const float* b2 = (const float*)d_in[4];
    const float* cb = (const float*)d_in[5];

    cudaFuncSetAttribute(encoder_fast,
                         cudaFuncAttributeMaxDynamicSharedMemorySize,
                         FAST_SMEM_BYTES);
    cudaFuncSetAttribute(exact_chunk,
                         cudaFuncAttributeMaxDynamicSharedMemorySize,
                         EX_SMEM_BYTES);

    float* out_zq  = (float*)d_out;
    float* out_idx = (float*)d_out + (size_t)B_SZ*LAT;
    int write_zq = 1, write_idx = 1;
    if (out_size >= B_SZ*(LAT + NQ)) {
    } else if (out_size >= B_SZ*LAT) {
        write_idx = 0;
    } else {
        write_zq = 0;
        out_idx  = (float*)d_out;
    }

    const int total = NBFRAG + KTOT*LAT + NQ*NEMB;
    prep_kernel<<<(total + 255)/256, 256>>>(w2, cb);
    encoder_fast<<<TILES_TOT, 256, FAST_SMEM_BYTES>>>(x, w1, b1, b2);
    rvq_flag<<<B_SZ/8, 256>>>(cb, out_zq, out_idx, write_zq, write_idx);
    exact_chunk<<<TILES_TOT, 256, EX_SMEM_BYTES>>>(x, w1, b1, b2);
    fix_reduce<<<(B_SZ*LAT + 255)/256, 256>>>();
    rvq_fix<<<B_SZ/8, 256>>>(cb, out_zq, out_idx, write_zq, write_idx);
}

// round 16
// speedup vs baseline: 1.1542x; 1.0321x over previous
#include <cuda_runtime.h>
#include <cuda_fp16.h>
#include <math_constants.h>
#include <cstdint>

#define B_SZ  2048
#define FEAT  840
#define HID   256
#define LAT   128
#define NQ    12
#define NEMB  512
#define KTOT  768

#define NT        7
#define TILE_T    128
#define TILES_TOT (B_SZ*NT)           /* 14336 */
#define NCHK      24
#define CHUNK_U32 4096                /* B frag words per chunk */
#define NBFRAG    (NCHK*CHUNK_U32)    /* 98304 */

#define MARGIN 3e-7f

typedef unsigned long long ull;

// ----------------------------- device scratch ------------------------------
__device__ __align__(16) uint32_t g_Bfrag[NBFRAG];   // w2 fp16 2-split frags
__device__ __align__(16) float g_w2t[KTOT*LAT];      // exact path [(k*256+c)][l]
__device__ float  g_cnorm[NQ*NEMB];
__device__ double g_zpart[(size_t)TILES_TOT*LAT];
__device__ __align__(16) float g_z[B_SZ*LAT];
__device__ int g_flagcnt;
__device__ int g_flaglist[B_SZ];

__device__ __forceinline__ float fp16_split_val(float v, int split){
    float h = __half2float(__float2half_rn(v));
    if (split == 0) return h;
    return v - h;
}

__device__ __forceinline__ void mma_fp16(float* d, const uint32_t* a, const uint32_t* b){
    asm volatile(
        "mma.sync.aligned.m16n8k16.row.col.f32.f16.f16.f32 "
        "{%0,%1,%2,%3}, {%4,%5,%6,%7}, {%8,%9}, {%0,%1,%2,%3};"
        : "+f"(d[0]), "+f"(d[1]), "+f"(d[2]), "+f"(d[3])
        : "r"(a[0]), "r"(a[1]), "r"(a[2]), "r"(a[3]), "r"(b[0]), "r"(b[1]));
}

__device__ __forceinline__ void ldmatrix_x4(uint32_t* r, uint32_t addr){
    asm volatile(
        "ldmatrix.sync.aligned.m8n8.x4.shared.b16 {%0,%1,%2,%3}, [%4];"
        : "=r"(r[0]), "=r"(r[1]), "=r"(r[2]), "=r"(r[3]) : "r"(addr));
}

__device__ __forceinline__ uint32_t smem_u32(const void* p){
    uint32_t a;
    asm("{ .reg .u64 t; cvta.to.shared.u64 t, %1; cvt.u32.u64 %0, t; }"
        : "=r"(a) : "l"(p));
    return a;
}

// ------------------------------- prep kernel -------------------------------
// B layout (u32 within chunk): idx = ((ks*16+nt)*32+lane)*4 + split*2 + reg
__global__ void prep_kernel(const float* __restrict__ w2,
                            const float* __restrict__ cb)
{
    int i = blockIdx.x * blockDim.x + threadIdx.x;
    if (i == 0) g_flagcnt = 0;
    if (i < NBFRAG) {
        int reg   = i & 1;
        int split = (i >> 1) & 1;
        int lane  = (i >> 2) & 31;
        int nt    = (i >> 7) & 15;
        int ks    = (i >> 11) & 1;
        int s     = i >> 12;
        int gr = lane >> 2, gc = lane & 3;
        int l  = nt*8 + gr;
        int tap = s >> 3;
        int c0 = (s & 7)*32 + ks*16 + gc*2 + reg*8;
        float v0 = w2[l*768 + c0*3 + tap];
        float v1 = w2[l*768 + (c0+1)*3 + tap];
        uint32_t lo = (uint32_t)__half_as_ushort(__float2half_rn(fp16_split_val(v0, split)));
        uint32_t hi = (uint32_t)__half_as_ushort(__float2half_rn(fp16_split_val(v1, split)));
        g_Bfrag[i] = lo | (hi << 16);
    } else if (i < NBFRAG + KTOT*LAT) {
        int j = i - NBFRAG;
        int l  = j & 127;
        int kk = j >> 7;
        int c  = kk & 255;
        int k  = kk >> 8;
        g_w2t[j] = w2[l*KTOT + c*3 + k];
    } else {
        int j = i - NBFRAG - KTOT*LAT;
        if (j < NQ*NEMB) {
            const float4* row = (const float4*)(cb + (size_t)j*LAT);
            float s = 0.f;
            #pragma unroll
            for (int m = 0; m < LAT/4; m++) {
                float4 v = row[m];
                s = __fmaf_rn(v.x, v.x, s);
                s = __fmaf_rn(v.y, v.y, s);
                s = __fmaf_rn(v.z, v.z, s);
                s = __fmaf_rn(v.w, v.w, s);
            }
            g_cnorm[j] = s;
        }
    }
}

// ---------- fast encoder (fp16 x3, cc-major, gen-once, ldmatrix) -----------
#define FXS_O   0                 /* 136 floats */
#define FW1_O   136
#define FB1_O   (136+768)
#define FB2_O   (136+768+256)     /* 1160 */
#define R1H_O   1288              /* 132 rows x 40 halves = 2640 floats */
#define R1L_O   (R1H_O + 2640)    /* 3928 */
#define FB_O    (R1L_O + 2640)    /* 6568; 3 x 4096 u32 */
#define FAST_SMEM_FLOATS (FB_O + 3*4096)   /* 18856 -> 75424 B */
#define FAST_SMEM_BYTES  (FAST_SMEM_FLOATS*4)
#define RSH     40                /* r1 row stride in halves (80 B) */

__global__ void __launch_bounds__(256, 2)
encoder_fast(const float* __restrict__ x,  const float* __restrict__ w1,
             const float* __restrict__ b1, const float* __restrict__ b2)
{
    extern __shared__ float sm[];
    char* smc = (char*)sm;
    uint32_t* Bsm = (uint32_t*)(sm + FB_O);
    __half* r1h = (__half*)(smc + R1H_O*4);
    __half* r1l = (__half*)(smc + R1L_O*4);

    const int tid  = threadIdx.x;
    const int lane = tid & 31;
    const int wid  = tid >> 5;
    const int wm   = wid & 3;          // warp rows: wm*32 .. +31
    const int wn   = wid >> 2;         // warp cols: wn*64 .. +63

    const int g  = blockIdx.x;
    const int b  = g / NT;
    const int t0 = (g % NT) * TILE_T;

    if (tid < 136) {
        int t = t0 - 2 + tid;
        sm[FXS_O + tid] = ((unsigned)t < (unsigned)FEAT)
                        ? x[(size_t)b*FEAT + t] : 0.f;
    }
    for (int i = tid; i < HID*3; i += 256) sm[FW1_O + i] = w1[i];
    if (tid < HID) sm[FB1_O + tid] = b1[tid];
    if (tid < LAT) sm[FB2_O + tid] = b2[tid];

    float acc[2][8][4];
    #pragma unroll
    for (int mi = 0; mi < 2; mi++)
        #pragma unroll
        for (int j = 0; j < 8; j++)
            #pragma unroll
            for (int r = 0; r < 4; r++) acc[mi][j][r] = 0.f;

    // ldmatrix lane mapping
    const int rowit = (lane & 7) + ((lane >> 3) & 1)*8;   // 0..15
    const int chsel = lane >> 4;                          // 0..1
    const uint32_t smbR1H = smem_u32(smc + R1H_O*4);
    const uint32_t smbR1L = smem_u32(smc + R1L_O*4);

    __syncthreads();

    for (int cc = 0; cc < 8; cc++) {
        __syncthreads();   // buffers free of prior readers

        // ---- stage B for all 3 taps of this cc (48 KB) ----
        #pragma unroll
        for (int tap = 0; tap < 3; tap++) {
            const uint4* src = (const uint4*)(g_Bfrag + (tap*8 + cc)*CHUNK_U32);
            uint4* dst = (uint4*)(Bsm + tap*4096);
            #pragma unroll
            for (int r = 0; r < 4; r++) dst[tid + r*256] = src[tid + r*256];
        }

        // ---- gen r1 ONCE for this cc: rows tt=0..129 (u = t0+tt-1) ----
        {
            const int c   = cc*32 + lane;
            const float wa = sm[FW1_O + c*3 + 0];
            const float wb = sm[FW1_O + c*3 + 1];
            const float wc = sm[FW1_O + c*3 + 2];
            const float bb = sm[FB1_O + c];
            #pragma unroll
            for (int it = 0; it < 17; it++) {
                const int tt = wid + it*8;
                if (tt < 130) {
                    const int u = t0 + tt - 1;
                    float v = 0.f;
                    if ((unsigned)u < (unsigned)FEAT) {
                        v = __fmul_rn(wa, sm[FXS_O + tt]);
                        v = __fmaf_rn(wb, sm[FXS_O + tt + 1], v);
                        v = __fmaf_rn(wc, sm[FXS_O + tt + 2], v);
                        v = fmaxf(__fadd_rn(v, bb), 0.f);
                    }
                    __half hh = __float2half_rn(v);
                    float  hf = __half2float(hh);
                    __half lh = __float2half_rn(v - hf);
                    r1h[tt*RSH + lane] = hh;
                    r1l[tt*RSH + lane] = lh;
                }
            }
        }
        __syncthreads();

        // ---- 3 taps x 2 ks x 8 j MMA phase (no barriers inside) ----
        #pragma unroll
        for (int tap = 0; tap < 3; tap++) {
            const uint32_t* Bt = Bsm + tap*4096;
            #pragma unroll
            for (int ks = 0; ks < 2; ks++) {
                uint32_t aH[2][4], aL[2][4];
                #pragma unroll
                for (int mi = 0; mi < 2; mi++) {
                    const int tt = wm*32 + mi*16 + rowit + tap;
                    const uint32_t off = (uint32_t)(tt*80 + (ks*2 + chsel)*16);
                    ldmatrix_x4(aH[mi], smbR1H + off);
                    ldmatrix_x4(aL[mi], smbR1L + off);
                }
                #pragma unroll
                for (int j = 0; j < 8; j++) {
                    const int nt = wn*8 + j;
                    uint4 bq = *(const uint4*)(Bt + ((ks*16 + nt)*32 + lane)*4);
                    uint32_t bH[2] = {bq.x, bq.y};
                    uint32_t bL[2] = {bq.z, bq.w};
                    #pragma unroll
                    for (int mi = 0; mi < 2; mi++) {
                        mma_fp16(acc[mi][j], aH[mi], bH);   // hh
                        mma_fp16(acc[mi][j], aH[mi], bL);   // hl
                        mma_fp16(acc[mi][j], aL[mi], bH);   // lh
                    }
                }
            }
        }
    }

    // ---- epilogue: relu(D + b2), fp64 fixed-order t-sum ----
    __syncthreads();
    double* dpart = (double*)(sm + R1H_O);   // r1 region dead

    const int qrow = lane >> 2;
    const int qcol = lane & 3;
    #pragma unroll
    for (int j = 0; j < 8; j++) {
        double s0 = 0.0, s1 = 0.0;
        const int l0 = wn*64 + j*8 + 2*qcol;
        const float bz0 = sm[FB2_O + l0];
        const float bz1 = sm[FB2_O + l0 + 1];
        #pragma unroll
        for (int mi = 0; mi < 2; mi++) {
            const int ra  = t0 + wm*32 + mi*16 + qrow;
            const int rb2 = ra + 8;
            if (ra < FEAT) {
                s0 += (double)fmaxf(__fadd_rn(acc[mi][j][0], bz0), 0.f);
                s1 += (double)fmaxf(__fadd_rn(acc[mi][j][1], bz1), 0.f);
            }
            if (rb2 < FEAT) {
                s0 += (double)fmaxf(__fadd_rn(acc[mi][j][2], bz0), 0.f);
                s1 += (double)fmaxf(__fadd_rn(acc[mi][j][3], bz1), 0.f);
            }
        }
        #pragma unroll
        for (int off = 4; off < 32; off <<= 1) {
            s0 += __shfl_xor_sync(0xffffffffu, s0, off);
            s1 += __shfl_xor_sync(0xffffffffu, s1, off);
        }
        if (qrow == 0) {
            dpart[wm*128 + l0]     = s0;
            dpart[wm*128 + l0 + 1] = s1;
        }
    }
    __syncthreads();
    if (tid < LAT) {
        double z = ((dpart[tid] + dpart[128 + tid]) + dpart[256 + tid]) + dpart[384 + tid];
        g_zpart[(size_t)g*LAT + tid] = z;
    }
}

// --------------------- RVQ core (proven, inlined) ---------------------------
__device__ __forceinline__ void rvq_row(const float* __restrict__ cb,
                                        float* res, float* qs, int* sidx,
                                        int lane, int flag_mode, int b_row)
{
    bool flagged = false;

    for (int q = 0; q < NQ; q++) {
        const float* cbq = cb + (size_t)q*NEMB*LAT;
        const float* cnq = g_cnorm + q*NEMB;

        float A;
        {
            float sA = 0.f;
            #pragma unroll
            for (int m = 0; m < 4; m++) {
                float rv = res[lane + 32*m];
                sA = __fmaf_rn(rv, rv, sA);
            }
            #pragma unroll
            for (int off = 16; off > 0; off >>= 1)
                sA = __fadd_rn(sA, __shfl_xor_sync(0xffffffffu, sA, off));
            A = sA;
        }

        float b1v = CUDART_INF_F, b2v = CUDART_INF_F;
        int   j1  = 0x7fffffff;
        #pragma unroll 1
        for (int jj = 0; jj < NEMB/32; jj++) {
            const int j = (lane << 4) + jj;
            const float4* crow = (const float4*)(cbq + (size_t)j*LAT);
            const float4* rrow = (const float4*)res;
            float dot = 0.f;
            #pragma unroll
            for (int m = 0; m < LAT/4; m++) {
                float4 cv = crow[m];
                float4 rv = rrow[m];
                dot = __fmaf_rn(cv.x, rv.x, dot);
                dot = __fmaf_rn(cv.y, rv.y, dot);
                dot = __fmaf_rn(cv.z, rv.z, dot);
                dot = __fmaf_rn(cv.w, rv.w, dot);
            }
            float t1 = __fmaf_rn(-2.f, dot, A);
            float d  = __fadd_rn(t1, cnq[j]);
            if (d < b1v) { b2v = b1v; b1v = d; j1 = j; }
            else if (d < b2v) { b2v = d; }
        }
        #pragma unroll
        for (int off = 16; off > 0; off >>= 1) {
            float ob1 = __shfl_xor_sync(0xffffffffu, b1v, off);
            int   oj1 = __shfl_xor_sync(0xffffffffu, j1,  off);
            float ob2 = __shfl_xor_sync(0xffffffffu, b2v, off);
            if (ob1 < b1v || (ob1 == b1v && oj1 < j1)) {
                b2v = fminf(b1v, ob2);
                b1v = ob1; j1 = oj1;
            } else {
                b2v = fminf(b2v, ob1);
            }
        }
        if (flag_mode && (b2v - b1v) < MARGIN) flagged = true;
        if (lane == 0) sidx[q] = j1;

        #pragma unroll
        for (int m = 0; m < 4; m++) {
            int d = lane + 32*m;
            float c = cbq[(size_t)j1*LAT + d];
            res[d] = __fadd_rn(res[d], -c);
            qs[m] = __fadd_rn(qs[m], c);
        }
        __syncwarp();
    }

    if (flag_mode && flagged && lane == 0) {
        int pos = atomicAdd(&g_flagcnt, 1);
        g_flaglist[pos] = b_row;
    }
}

// ------------- RVQ pass 1: fused z-reduce (fp64) + RVQ + flags --------------
__global__ void __launch_bounds__(256)
rvq_flag(const float* __restrict__ cb,
         float* __restrict__ out_zq, float* __restrict__ out_idx,
         int write_zq, int write_idx)
{
    __shared__ __align__(16) float res[8][LAT];
    __shared__ int sidx[8][NQ];

    const int tid  = threadIdx.x;
    const int w    = tid >> 5;
    const int lane = tid & 31;
    const int b    = blockIdx.x * 8 + w;

    float qs[4] = {0.f, 0.f, 0.f, 0.f};
    #pragma unroll
    for (int m = 0; m < 4; m++) {
        const int d = lane + 32*m;
        double s = 0.0;
        #pragma unroll
        for (int t = 0; t < NT; t++)
            s += g_zpart[(size_t)(b*NT + t)*LAT + d];
        res[w][d] = __fdiv_rn((float)s, (float)FEAT);
    }
    __syncwarp();

    rvq_row(cb, res[w], qs, sidx[w], lane, 1, b);

    if (write_zq) {
        #pragma unroll
        for (int m = 0; m < 4; m++)
            out_zq[(size_t)b*LAT + lane + 32*m] = qs[m];
    }
    if (write_idx && lane < NQ)
        out_idx[(size_t)b*NQ + lane] = (float)sidx[w][lane];
}

// -------------------- exact encoder chunk (bit-exact chain) -----------------
#define TCX   128
#define CG    64
#define RSP   132
#define EXS_O   0
#define EW1_O   844
#define EB1_O   (844+768)
#define ER1_O   (844+768+256)
#define EW2T_O  (ER1_O + CG*RSP*2)
#define EX_SMEM_FLOATS (EW2T_O + CG*LAT)
#define EX_SMEM_BYTES  (EX_SMEM_FLOATS*4)

__device__ __forceinline__ ull ffma2(ull a, ull b, ull c){
    ull d;
    asm("fma.rn.f32x2 %0, %1, %2, %3;" : "=l"(d) : "l"(a), "l"(b), "l"(c));
    return d;
}
__device__ __forceinline__ float2 unpack2(ull v){
    float2 f; asm("mov.b64 {%0,%1}, %2;" : "=f"(f.x), "=f"(f.y) : "l"(v));
    return f;
}
__device__ __forceinline__ ull splat2(float v){
    ull d; asm("mov.b64 %0, {%1,%1};" : "=l"(d) : "f"(v));
    return d;
}

__global__ void __launch_bounds__(256, 2)
exact_chunk(const float* __restrict__ x,  const float* __restrict__ w1,
            const float* __restrict__ b1, const float* __restrict__ b2)
{
    const int cnt = g_flagcnt;
    const int i   = blockIdx.x;
    if (i >= cnt * NT) return;
    const int b  = g_flaglist[i / NT];
    const int ch = i % NT;

    extern __shared__ float sm[];
    float* xs  = sm + EXS_O;
    float* w1s = sm + EW1_O;
    float* b1s = sm + EB1_O;
    ull*   r1s2 = (ull*)(sm + ER1_O);
    const ulonglong2* wt = (const ulonglong2*)(sm + EW2T_O);

    const int tid  = threadIdx.x;
    const int lane = tid & 31;
    const int w8   = tid >> 5;
    const int l0   = lane * 4;
    const int gcc  = tid >> 2;
    const int gsub = tid & 3;

    for (int ii = tid; ii < FEAT; ii += 256) xs[ii + 1] = x[(size_t)b*FEAT + ii];
    for (int ii = tid; ii < HID*3; ii += 256) w1s[ii] = w1[ii];
    if (tid < HID) b1s[tid] = b1[tid];
    if (tid == 0) { xs[0] = 0.f; xs[FEAT + 1] = 0.f; xs[FEAT + 2] = 0.f; }

    float bl[4];
    #pragma unroll
    for (int j = 0; j < 4; j++) bl[j] = b2[l0 + j];

    double zp[4] = {0.0, 0.0, 0.0, 0.0};
    __syncthreads();

    const int t0 = ch * TCX;

    ull acc[2][16];
    #pragma unroll
    for (int p = 0; p < 2; p++)
        #pragma unroll
        for (int ii = 0; ii < 16; ii++) acc[p][ii] = 0ull;

    for (int g = 0; g < 4; g++) {
        __syncthreads();
        {
            const int c  = g*CG + gcc;
            const float wa = w1s[c*3+0], wb = w1s[c*3+1], wc = w1s[c*3+2];
            const float bb1 = b1s[c];
            #pragma unroll
            for (int s = 0; s < 33; s++) {
                int tt = gsub + 4*s;
                if (tt < TCX + 2) {
                    int t = t0 - 1 + tt;
                    float v = 0.f;
                    if ((unsigned)t < (unsigned)FEAT) {
                        v = __fmul_rn(wa, xs[t]);
                        v = __fmaf_rn(wb, xs[t+1], v);
                        v = __fmaf_rn(wc, xs[t+2], v);
                        v = fmaxf(__fadd_rn(v, bb1), 0.f);
                    }
                    r1s2[gcc*RSP + tt] = splat2(v);
                }
            }
        }

        #pragma unroll
        for (int k = 0; k < 3; k++) {
            __syncthreads();
            {
                const float4* src = (const float4*)(g_w2t + (size_t)(k*HID + g*CG)*LAT);
                float4* dst = (float4*)(sm + EW2T_O);
                #pragma unroll
                for (int r = 0; r < 8; r++) dst[tid + r*256] = src[tid + r*256];
            }
            __syncthreads();

            #pragma unroll 2
            for (int kk = 0; kk < CG; kk++) {
                ulonglong2 a2 = wt[kk*32 + lane];
                const ulonglong2* brow =
                    (const ulonglong2*)(r1s2 + kk*RSP) + w8*8;
                #pragma unroll
                for (int j = 0; j < 9; j++) {
                    ulonglong2 bb = brow[j];
                    const int i0 = 2*j - k;
                    const int i1 = 2*j + 1 - k;
                    if (i0 >= 0 && i0 < 16) {
                        acc[0][i0] = ffma2(a2.x, bb.x, acc[0][i0]);
                        acc[1][i0] = ffma2(a2.y, bb.x, acc[1][i0]);
                    }
                    if (i1 >= 0 && i1 < 16) {
                        acc[0][i1] = ffma2(a2.x, bb.y, acc[0][i1]);
                        acc[1][i1] = ffma2(a2.y, bb.y, acc[1][i1]);
                    }
                }
            }
        }
    }

    #pragma unroll
    for (int ii = 0; ii < 16; ii++) {
        if (t0 + w8*16 + ii < FEAT) {
            #pragma unroll
            for (int p = 0; p < 2; p++) {
                float2 f = unpack2(acc[p][ii]);
                zp[2*p+0] += (double)fmaxf(__fadd_rn(f.x, bl[2*p+0]), 0.f);
                zp[2*p+1] += (double)fmaxf(__fadd_rn(f.y, bl[2*p+1]), 0.f);
            }
        }
    }

    __syncthreads();
    double* dp = (double*)(sm + ER1_O);
    #pragma unroll
    for (int j = 0; j < 4; j++) dp[w8*128 + l0 + j] = zp[j];
    __syncthreads();
    if (tid < LAT) {
        double v = dp[tid];
        #pragma unroll
        for (int w = 1; w < 8; w++) v += dp[w*128 + tid];
        g_zpart[(size_t)(b*NT + ch)*LAT + tid] = v;
    }
}

// --------------------- fixed rows: reduce + RVQ redo ------------------------
__global__ void fix_reduce()
{
    int idx = blockIdx.x * blockDim.x + threadIdx.x;
    int p = idx >> 7;
    if (p >= g_flagcnt) return;
    int b = g_flaglist[p];
    int l = idx & 127;
    double s = 0.0;
    #pragma unroll
    for (int t = 0; t < NT; t++)
        s += g_zpart[(size_t)(b*NT + t)*LAT + l];
    g_z[(size_t)b*LAT + l] = __fdiv_rn((float)s, (float)FEAT);
}

__global__ void __launch_bounds__(256)
rvq_fix(const float* __restrict__ cb,
        float* __restrict__ out_zq, float* __restrict__ out_idx,
        int write_zq, int write_idx)
{
    __shared__ __align__(16) float res[8][LAT];
    __shared__ int sidx[8][NQ];

    const int tid  = threadIdx.x;
    const int w    = tid >> 5;
    const int lane = tid & 31;
    const int slot = blockIdx.x * 8 + w;
    if (slot >= g_flagcnt) return;
    const int b = g_flaglist[slot];

    float qs[4] = {0.f, 0.f, 0.f, 0.f};
    #pragma unroll
    for (int m = 0; m < 4; m++)
        res[w][lane + 32*m] = g_z[(size_t)b*LAT + lane + 32*m];
    __syncwarp();

    rvq_row(cb, res[w], qs, sidx[w], lane, 0, b);

    if (write_zq) {
        #pragma unroll
        for (int m = 0; m < 4; m++)
            out_zq[(size_t)b*LAT + lane + 32*m] = qs[m];
    }
    if (write_idx && lane < NQ)
        out_idx[(size_t)b*NQ + lane] = (float)sidx[w][lane];
}

// ---------------------------------------------------------------------------
extern "C" void kernel_launch(void* const* d_in, const int* in_sizes, int n_in,
                              void* d_out, int out_size)
{
    const float* x  = (const float*)d_in[0];
    const float* w1 = (const float*)d_in[1];
    const float* b1 = (const float*)d_in[2];
    const float* w2 = (const float*)d_in[3];
    const float* b2 = (const float*)d_in[4];
    const float* cb = (const float*)d_in[5];

    cudaFuncSetAttribute(encoder_fast,
                         cudaFuncAttributeMaxDynamicSharedMemorySize,
                         FAST_SMEM_BYTES);
    cudaFuncSetAttribute(exact_chunk,
                         cudaFuncAttributeMaxDynamicSharedMemorySize,
                         EX_SMEM_BYTES);

    float* out_zq  = (float*)d_out;
    float* out_idx = (float*)d_out + (size_t)B_SZ*LAT;
    int write_zq = 1, write_idx = 1;
    if (out_size >= B_SZ*(LAT + NQ)) {
    } else if (out_size >= B_SZ*LAT) {
        write_idx = 0;
    } else {
        write_zq = 0;
        out_idx  = (float*)d_out;
    }

    const int total = NBFRAG + KTOT*LAT + NQ*NEMB;
    prep_kernel<<<(total + 255)/256, 256>>>(w2, cb);
    encoder_fast<<<TILES_TOT, 256, FAST_SMEM_BYTES>>>(x, w1, b1, b2);
    rvq_flag<<<B_SZ/8, 256>>>(cb, out_zq, out_idx, write_zq, write_idx);
    exact_chunk<<<TILES_TOT, 256, EX_SMEM_BYTES>>>(x, w1, b1, b2);
    fix_reduce<<<(B_SZ*LAT + 255)/256, 256>>>();
    rvq_fix<<<B_SZ/8, 256>>>(cb, out_zq, out_idx, write_zq, write_idx);
}

// round 17
// speedup vs baseline: 1.2504x; 1.0834x over previous
#include <cuda_runtime.h>
#include <cuda_fp16.h>
#include <math_constants.h>
#include <cstdint>

#define B_SZ  2048
#define FEAT  840
#define HID   256
#define LAT   128
#define NQ    12
#define NEMB  512
#define KTOT  768

#define NT        7
#define TILE_T    128
#define TILES_TOT (B_SZ*NT)           /* 14336 */
#define NCHK      24
#define CHUNK_U32 4096                /* B frag words per chunk */
#define NBFRAG    (NCHK*CHUNK_U32)    /* 98304 */

#define MARGIN 1e-7f

typedef unsigned long long ull;

// ----------------------------- device scratch ------------------------------
__device__ __align__(16) uint32_t g_Bfrag[NBFRAG];   // w2 fp16 2-split frags
__device__ __align__(16) float g_w2t[KTOT*LAT];      // exact path [(k*256+c)][l]
__device__ float  g_cnorm[NQ*NEMB];
__device__ double g_zpart[(size_t)TILES_TOT*LAT];
__device__ __align__(16) float g_z[B_SZ*LAT];
__device__ int g_flagcnt;
__device__ int g_flaglist[B_SZ];

__device__ __forceinline__ float fp16_split_val(float v, int split){
    float h = __half2float(__float2half_rn(v));
    if (split == 0) return h;
    return v - h;
}

__device__ __forceinline__ void mma_fp16(float* d, const uint32_t* a, const uint32_t* b){
    asm volatile(
        "mma.sync.aligned.m16n8k16.row.col.f32.f16.f16.f32 "
        "{%0,%1,%2,%3}, {%4,%5,%6,%7}, {%8,%9}, {%0,%1,%2,%3};"
        : "+f"(d[0]), "+f"(d[1]), "+f"(d[2]), "+f"(d[3])
        : "r"(a[0]), "r"(a[1]), "r"(a[2]), "r"(a[3]), "r"(b[0]), "r"(b[1]));
}

__device__ __forceinline__ void ldmatrix_x4(uint32_t* r, uint32_t addr){
    asm volatile(
        "ldmatrix.sync.aligned.m8n8.x4.shared.b16 {%0,%1,%2,%3}, [%4];"
        : "=r"(r[0]), "=r"(r[1]), "=r"(r[2]), "=r"(r[3]) : "r"(addr));
}

__device__ __forceinline__ uint32_t smem_u32(const void* p){
    uint32_t a;
    asm("{ .reg .u64 t; cvta.to.shared.u64 t, %1; cvt.u32.u64 %0, t; }"
        : "=r"(a) : "l"(p));
    return a;
}

// ------------------------------- prep kernel -------------------------------
// B layout (u32 within chunk): idx = ((ks*16+nt)*32+lane)*4 + split*2 + reg
__global__ void prep_kernel(const float* __restrict__ w2,
                            const float* __restrict__ cb)
{
    int i = blockIdx.x * blockDim.x + threadIdx.x;
    if (i == 0) g_flagcnt = 0;
    if (i < NBFRAG) {
        int reg   = i & 1;
        int split = (i >> 1) & 1;
        int lane  = (i >> 2) & 31;
        int nt    = (i >> 7) & 15;
        int ks    = (i >> 11) & 1;
        int s     = i >> 12;
        int gr = lane >> 2, gc = lane & 3;
        int l  = nt*8 + gr;
        int tap = s >> 3;
        int c0 = (s & 7)*32 + ks*16 + gc*2 + reg*8;
        float v0 = w2[l*768 + c0*3 + tap];
        float v1 = w2[l*768 + (c0+1)*3 + tap];
        uint32_t lo = (uint32_t)__half_as_ushort(__float2half_rn(fp16_split_val(v0, split)));
        uint32_t hi = (uint32_t)__half_as_ushort(__float2half_rn(fp16_split_val(v1, split)));
        g_Bfrag[i] = lo | (hi << 16);
    } else if (i < NBFRAG + KTOT*LAT) {
        int j = i - NBFRAG;
        int l  = j & 127;
        int kk = j >> 7;
        int c  = kk & 255;
        int k  = kk >> 8;
        g_w2t[j] = w2[l*KTOT + c*3 + k];
    } else {
        int j = i - NBFRAG - KTOT*LAT;
        if (j < NQ*NEMB) {
            const float4* row = (const float4*)(cb + (size_t)j*LAT);
            float s = 0.f;
            #pragma unroll
            for (int m = 0; m < LAT/4; m++) {
                float4 v = row[m];
                s = __fmaf_rn(v.x, v.x, s);
                s = __fmaf_rn(v.y, v.y, s);
                s = __fmaf_rn(v.z, v.z, s);
                s = __fmaf_rn(v.w, v.w, s);
            }
            g_cnorm[j] = s;
        }
    }
}

// ------ fast encoder (fp16 x3, cc-major, gen-once, ldmatrix, B via L1) -----
#define FXS_O   0                 /* 136 floats */
#define FW1_O   136
#define FB1_O   (136+768)
#define FB2_O   (136+768+256)     /* 1160 */
#define R1H_O   1288              /* 132 rows x 40 halves = 2640 floats */
#define R1L_O   (R1H_O + 2640)    /* 3928 */
#define FAST_SMEM_FLOATS (R1L_O + 2640)    /* 6568 -> 26272 B */
#define FAST_SMEM_BYTES  (FAST_SMEM_FLOATS*4)
#define RSH     40                /* r1 row stride in halves (80 B) */

__global__ void __launch_bounds__(256, 2)
encoder_fast(const float* __restrict__ x,  const float* __restrict__ w1,
             const float* __restrict__ b1, const float* __restrict__ b2)
{
    extern __shared__ float sm[];
    char* smc = (char*)sm;
    __half* r1h = (__half*)(smc + R1H_O*4);
    __half* r1l = (__half*)(smc + R1L_O*4);

    const int tid  = threadIdx.x;
    const int lane = tid & 31;
    const int wid  = tid >> 5;
    const int wm   = wid & 3;          // warp rows: wm*32 .. +31
    const int wn   = wid >> 2;         // warp cols: wn*64 .. +63

    const int g  = blockIdx.x;
    const int b  = g / NT;
    const int t0 = (g % NT) * TILE_T;

    if (tid < 136) {
        int t = t0 - 2 + tid;
        sm[FXS_O + tid] = ((unsigned)t < (unsigned)FEAT)
                        ? x[(size_t)b*FEAT + t] : 0.f;
    }
    for (int i = tid; i < HID*3; i += 256) sm[FW1_O + i] = w1[i];
    if (tid < HID) sm[FB1_O + tid] = b1[tid];
    if (tid < LAT) sm[FB2_O + tid] = b2[tid];

    float acc[2][8][4];
    #pragma unroll
    for (int mi = 0; mi < 2; mi++)
        #pragma unroll
        for (int j = 0; j < 8; j++)
            #pragma unroll
            for (int r = 0; r < 4; r++) acc[mi][j][r] = 0.f;

    // ldmatrix lane mapping
    const int rowit = (lane & 7) + ((lane >> 3) & 1)*8;   // 0..15
    const int chsel = lane >> 4;                          // 0..1
    const uint32_t smbR1H = smem_u32(smc + R1H_O*4);
    const uint32_t smbR1L = smem_u32(smc + R1L_O*4);

    __syncthreads();

    for (int cc = 0; cc < 8; cc++) {
        __syncthreads();   // r1 buffers free of prior readers

        // ---- gen r1 ONCE for this cc: rows tt=0..129 (u = t0+tt-1) ----
        {
            const int c   = cc*32 + lane;
            const float wa = sm[FW1_O + c*3 + 0];
            const float wb = sm[FW1_O + c*3 + 1];
            const float wc = sm[FW1_O + c*3 + 2];
            const float bb = sm[FB1_O + c];
            #pragma unroll
            for (int it = 0; it < 17; it++) {
                const int tt = wid + it*8;
                if (tt < 130) {
                    const int u = t0 + tt - 1;
                    float v = 0.f;
                    if ((unsigned)u < (unsigned)FEAT) {
                        v = __fmul_rn(wa, sm[FXS_O + tt]);
                        v = __fmaf_rn(wb, sm[FXS_O + tt + 1], v);
                        v = __fmaf_rn(wc, sm[FXS_O + tt + 2], v);
                        v = fmaxf(__fadd_rn(v, bb), 0.f);
                    }
                    __half hh = __float2half_rn(v);
                    float  hf = __half2float(hh);
                    __half lh = __float2half_rn(v - hf);
                    r1h[tt*RSH + lane] = hh;
                    r1l[tt*RSH + lane] = lh;
                }
            }
        }
        __syncthreads();

        // ---- 3 taps x 2 ks x 8 j MMA phase; B direct from L1/L2 ----
        #pragma unroll
        for (int tap = 0; tap < 3; tap++) {
            const uint4* Bt = (const uint4*)(g_Bfrag + (tap*8 + cc)*CHUNK_U32);
            #pragma unroll
            for (int ks = 0; ks < 2; ks++) {
                uint32_t aH[2][4], aL[2][4];
                #pragma unroll
                for (int mi = 0; mi < 2; mi++) {
                    const int tt = wm*32 + mi*16 + rowit + tap;
                    const uint32_t off = (uint32_t)(tt*80 + (ks*2 + chsel)*16);
                    ldmatrix_x4(aH[mi], smbR1H + off);
                    ldmatrix_x4(aL[mi], smbR1L + off);
                }
                #pragma unroll
                for (int j = 0; j < 8; j++) {
                    const int nt = wn*8 + j;
                    uint4 bq = __ldg(Bt + (ks*16 + nt)*32 + lane);
                    uint32_t bH[2] = {bq.x, bq.y};
                    uint32_t bL[2] = {bq.z, bq.w};
                    #pragma unroll
                    for (int mi = 0; mi < 2; mi++) {
                        mma_fp16(acc[mi][j], aH[mi], bH);   // hh
                        mma_fp16(acc[mi][j], aH[mi], bL);   // hl
                        mma_fp16(acc[mi][j], aL[mi], bH);   // lh
                    }
                }
            }
        }
    }

    // ---- epilogue: relu(D + b2), fp64 fixed-order t-sum ----
    __syncthreads();
    double* dpart = (double*)(sm + R1H_O);   // r1 region dead

    const int qrow = lane >> 2;
    const int qcol = lane & 3;
    #pragma unroll
    for (int j = 0; j < 8; j++) {
        double s0 = 0.0, s1 = 0.0;
        const int l0 = wn*64 + j*8 + 2*qcol;
        const float bz0 = sm[FB2_O + l0];
        const float bz1 = sm[FB2_O + l0 + 1];
        #pragma unroll
        for (int mi = 0; mi < 2; mi++) {
            const int ra  = t0 + wm*32 + mi*16 + qrow;
            const int rb2 = ra + 8;
            if (ra < FEAT) {
                s0 += (double)fmaxf(__fadd_rn(acc[mi][j][0], bz0), 0.f);
                s1 += (double)fmaxf(__fadd_rn(acc[mi][j][1], bz1), 0.f);
            }
            if (rb2 < FEAT) {
                s0 += (double)fmaxf(__fadd_rn(acc[mi][j][2], bz0), 0.f);
                s1 += (double)fmaxf(__fadd_rn(acc[mi][j][3], bz1), 0.f);
            }
        }
        #pragma unroll
        for (int off = 4; off < 32; off <<= 1) {
            s0 += __shfl_xor_sync(0xffffffffu, s0, off);
            s1 += __shfl_xor_sync(0xffffffffu, s1, off);
        }
        if (qrow == 0) {
            dpart[wm*128 + l0]     = s0;
            dpart[wm*128 + l0 + 1] = s1;
        }
    }
    __syncthreads();
    if (tid < LAT) {
        double z = ((dpart[tid] + dpart[128 + tid]) + dpart[256 + tid]) + dpart[384 + tid];
        g_zpart[(size_t)g*LAT + tid] = z;
    }
}

// --------------------- RVQ core (proven, inlined) ---------------------------
__device__ __forceinline__ void rvq_row(const float* __restrict__ cb,
                                        float* res, float* qs, int* sidx,
                                        int lane, int flag_mode, int b_row)
{
    bool flagged = false;

    for (int q = 0; q < NQ; q++) {
        const float* cbq = cb + (size_t)q*NEMB*LAT;
        const float* cnq = g_cnorm + q*NEMB;

        float A;
        {
            float sA = 0.f;
            #pragma unroll
            for (int m = 0; m < 4; m++) {
                float rv = res[lane + 32*m];
                sA = __fmaf_rn(rv, rv, sA);
            }
            #pragma unroll
            for (int off = 16; off > 0; off >>= 1)
                sA = __fadd_rn(sA, __shfl_xor_sync(0xffffffffu, sA, off));
            A = sA;
        }

        float b1v = CUDART_INF_F, b2v = CUDART_INF_F;
        int   j1  = 0x7fffffff;
        #pragma unroll 1
        for (int jj = 0; jj < NEMB/32; jj++) {
            const int j = (lane << 4) + jj;
            const float4* crow = (const float4*)(cbq + (size_t)j*LAT);
            const float4* rrow = (const float4*)res;
            float dot = 0.f;
            #pragma unroll
            for (int m = 0; m < LAT/4; m++) {
                float4 cv = crow[m];
                float4 rv = rrow[m];
                dot = __fmaf_rn(cv.x, rv.x, dot);
                dot = __fmaf_rn(cv.y, rv.y, dot);
                dot = __fmaf_rn(cv.z, rv.z, dot);
                dot = __fmaf_rn(cv.w, rv.w, dot);
            }
            float t1 = __fmaf_rn(-2.f, dot, A);
            float d  = __fadd_rn(t1, cnq[j]);
            if (d < b1v) { b2v = b1v; b1v = d; j1 = j; }
            else if (d < b2v) { b2v = d; }
        }
        #pragma unroll
        for (int off = 16; off > 0; off >>= 1) {
            float ob1 = __shfl_xor_sync(0xffffffffu, b1v, off);
            int   oj1 = __shfl_xor_sync(0xffffffffu, j1,  off);
            float ob2 = __shfl_xor_sync(0xffffffffu, b2v, off);
            if (ob1 < b1v || (ob1 == b1v && oj1 < j1)) {
                b2v = fminf(b1v, ob2);
                b1v = ob1; j1 = oj1;
            } else {
                b2v = fminf(b2v, ob1);
            }
        }
        if (flag_mode && (b2v - b1v) < MARGIN) flagged = true;
        if (lane == 0) sidx[q] = j1;

        #pragma unroll
        for (int m = 0; m < 4; m++) {
            int d = lane + 32*m;
            float c = cbq[(size_t)j1*LAT + d];
            res[d] = __fadd_rn(res[d], -c);
            qs[m] = __fadd_rn(qs[m], c);
        }
        __syncwarp();
    }

    if (flag_mode && flagged && lane == 0) {
        int pos = atomicAdd(&g_flagcnt, 1);
        g_flaglist[pos] = b_row;
    }
}

// ------------- RVQ pass 1: fused z-reduce (fp64) + RVQ + flags --------------
__global__ void __launch_bounds__(256)
rvq_flag(const float* __restrict__ cb,
         float* __restrict__ out_zq, float* __restrict__ out_idx,
         int write_zq, int write_idx)
{
    __shared__ __align__(16) float res[8][LAT];
    __shared__ int sidx[8][NQ];

    const int tid  = threadIdx.x;
    const int w    = tid >> 5;
    const int lane = tid & 31;
    const int b    = blockIdx.x * 8 + w;

    float qs[4] = {0.f, 0.f, 0.f, 0.f};
    #pragma unroll
    for (int m = 0; m < 4; m++) {
        const int d = lane + 32*m;
        double s = 0.0;
        #pragma unroll
        for (int t = 0; t < NT; t++)
            s += g_zpart[(size_t)(b*NT + t)*LAT + d];
        res[w][d] = __fdiv_rn((float)s, (float)FEAT);
    }
    __syncwarp();

    rvq_row(cb, res[w], qs, sidx[w], lane, 1, b);

    if (write_zq) {
        #pragma unroll
        for (int m = 0; m < 4; m++)
            out_zq[(size_t)b*LAT + lane + 32*m] = qs[m];
    }
    if (write_idx && lane < NQ)
        out_idx[(size_t)b*NQ + lane] = (float)sidx[w][lane];
}

// -------------------- exact encoder chunk (bit-exact chain) -----------------
#define TCX   128
#define CG    64
#define RSP   132
#define EXS_O   0
#define EW1_O   844
#define EB1_O   (844+768)
#define ER1_O   (844+768+256)
#define EW2T_O  (ER1_O + CG*RSP*2)
#define EX_SMEM_FLOATS (EW2T_O + CG*LAT)
#define EX_SMEM_BYTES  (EX_SMEM_FLOATS*4)

__device__ __forceinline__ ull ffma2(ull a, ull b, ull c){
    ull d;
    asm("fma.rn.f32x2 %0, %1, %2, %3;" : "=l"(d) : "l"(a), "l"(b), "l"(c));
    return d;
}
__device__ __forceinline__ float2 unpack2(ull v){
    float2 f; asm("mov.b64 {%0,%1}, %2;" : "=f"(f.x), "=f"(f.y) : "l"(v));
    return f;
}
__device__ __forceinline__ ull splat2(float v){
    ull d; asm("mov.b64 %0, {%1,%1};" : "=l"(d) : "f"(v));
    return d;
}

__global__ void __launch_bounds__(256, 2)
exact_chunk(const float* __restrict__ x,  const float* __restrict__ w1,
            const float* __restrict__ b1, const float* __restrict__ b2)
{
    const int cnt = g_flagcnt;
    const int i   = blockIdx.x;
    if (i >= cnt * NT) return;
    const int b  = g_flaglist[i / NT];
    const int ch = i % NT;

    extern __shared__ float sm[];
    float* xs  = sm + EXS_O;
    float* w1s = sm + EW1_O;
    float* b1s = sm + EB1_O;
    ull*   r1s2 = (ull*)(sm + ER1_O);
    const ulonglong2* wt = (const ulonglong2*)(sm + EW2T_O);

    const int tid  = threadIdx.x;
    const int lane = tid & 31;
    const int w8   = tid >> 5;
    const int l0   = lane * 4;
    const int gcc  = tid >> 2;
    const int gsub = tid & 3;

    for (int ii = tid; ii < FEAT; ii += 256) xs[ii + 1] = x[(size_t)b*FEAT + ii];
    for (int ii = tid; ii < HID*3; ii += 256) w1s[ii] = w1[ii];
    if (tid < HID) b1s[tid] = b1[tid];
    if (tid == 0) { xs[0] = 0.f; xs[FEAT + 1] = 0.f; xs[FEAT + 2] = 0.f; }

    float bl[4];
    #pragma unroll
    for (int j = 0; j < 4; j++) bl[j] = b2[l0 + j];

    double zp[4] = {0.0, 0.0, 0.0, 0.0};
    __syncthreads();

    const int t0 = ch * TCX;

    ull acc[2][16];
    #pragma unroll
    for (int p = 0; p < 2; p++)
        #pragma unroll
        for (int ii = 0; ii < 16; ii++) acc[p][ii] = 0ull;

    for (int g = 0; g < 4; g++) {
        __syncthreads();
        {
            const int c  = g*CG + gcc;
            const float wa = w1s[c*3+0], wb = w1s[c*3+1], wc = w1s[c*3+2];
            const float bb1 = b1s[c];
            #pragma unroll
            for (int s = 0; s < 33; s++) {
                int tt = gsub + 4*s;
                if (tt < TCX + 2) {
                    int t = t0 - 1 + tt;
                    float v = 0.f;
                    if ((unsigned)t < (unsigned)FEAT) {
                        v = __fmul_rn(wa, xs[t]);
                        v = __fmaf_rn(wb, xs[t+1], v);
                        v = __fmaf_rn(wc, xs[t+2], v);
                        v = fmaxf(__fadd_rn(v, bb1), 0.f);
                    }
                    r1s2[gcc*RSP + tt] = splat2(v);
                }
            }
        }

        #pragma unroll
        for (int k = 0; k < 3; k++) {
            __syncthreads();
            {
                const float4* src = (const float4*)(g_w2t + (size_t)(k*HID + g*CG)*LAT);
                float4* dst = (float4*)(sm + EW2T_O);
                #pragma unroll
                for (int r = 0; r < 8; r++) dst[tid + r*256] = src[tid + r*256];
            }
            __syncthreads();

            #pragma unroll 2
            for (int kk = 0; kk < CG; kk++) {
                ulonglong2 a2 = wt[kk*32 + lane];
                const ulonglong2* brow =
                    (const ulonglong2*)(r1s2 + kk*RSP) + w8*8;
                #pragma unroll
                for (int j = 0; j < 9; j++) {
                    ulonglong2 bb = brow[j];
                    const int i0 = 2*j - k;
                    const int i1 = 2*j + 1 - k;
                    if (i0 >= 0 && i0 < 16) {
                        acc[0][i0] = ffma2(a2.x, bb.x, acc[0][i0]);
                        acc[1][i0] = ffma2(a2.y, bb.x, acc[1][i0]);
                    }
                    if (i1 >= 0 && i1 < 16) {
                        acc[0][i1] = ffma2(a2.x, bb.y, acc[0][i1]);
                        acc[1][i1] = ffma2(a2.y, bb.y, acc[1][i1]);
                    }
                }
            }
        }
    }

    #pragma unroll
    for (int ii = 0; ii < 16; ii++) {
        if (t0 + w8*16 + ii < FEAT) {
            #pragma unroll
            for (int p = 0; p < 2; p++) {
                float2 f = unpack2(acc[p][ii]);
                zp[2*p+0] += (double)fmaxf(__fadd_rn(f.x, bl[2*p+0]), 0.f);
                zp[2*p+1] += (double)fmaxf(__fadd_rn(f.y, bl[2*p+1]), 0.f);
            }
        }
    }

    __syncthreads();
    double* dp = (double*)(sm + ER1_O);
    #pragma unroll
    for (int j = 0; j < 4; j++) dp[w8*128 + l0 + j] = zp[j];
    __syncthreads();
    if (tid < LAT) {
        double v = dp[tid];
        #pragma unroll
        for (int w = 1; w < 8; w++) v += dp[w*128 + tid];
        g_zpart[(size_t)(b*NT + ch)*LAT + tid] = v;
    }
}

// --------------------- fixed rows: reduce + RVQ redo ------------------------
__global__ void fix_reduce()
{
    int idx = blockIdx.x * blockDim.x + threadIdx.x;
    int p = idx >> 7;
    if (p >= g_flagcnt) return;
    int b = g_flaglist[p];
    int l = idx & 127;
    double s = 0.0;
    #pragma unroll
    for (int t = 0; t < NT; t++)
        s += g_zpart[(size_t)(b*NT + t)*LAT + l];
    g_z[(size_t)b*LAT + l] = __fdiv_rn((float)s, (float)FEAT);
}

__global__ void __launch_bounds__(256)
rvq_fix(const float* __restrict__ cb,
        float* __restrict__ out_zq, float* __restrict__ out_idx,
        int write_zq, int write_idx)
{
    __shared__ __align__(16) float res[8][LAT];
    __shared__ int sidx[8][NQ];

    const int tid  = threadIdx.x;
    const int w    = tid >> 5;
    const int lane = tid & 31;
    const int slot = blockIdx.x * 8 + w;
    if (slot >= g_flagcnt) return;
    const int b = g_flaglist[slot];

    float qs[4] = {0.f, 0.f, 0.f, 0.f};
    #pragma unroll
    for (int m = 0; m < 4; m++)
        res[w][lane + 32*m] = g_z[(size_t)b*LAT + lane + 32*m];
    __syncwarp();

    rvq_row(cb, res[w], qs, sidx[w], lane, 0, b);

    if (write_zq) {
        #pragma unroll
        for (int m = 0; m < 4; m++)
            out_zq[(size_t)b*LAT + lane + 32*m] = qs[m];
    }
    if (write_idx && lane < NQ)
        out_idx[(size_t)b*NQ + lane] = (float)sidx[w][lane];
}

// ---------------------------------------------------------------------------
extern "C" void kernel_launch(void* const* d_in, const int* in_sizes, int n_in,
                              void* d_out, int out_size)
{
    const float* x  = (const float*)d_in[0];
    const float* w1 = (const float*)d_in[1];
    const float* b1 = (const float*)d_in[2];
    const float* w2 = (const float*)d_in[3];
    const float* b2 = (const float*)d_in[4];
    const float* cb = (const float*)d_in[5];

    cudaFuncSetAttribute(encoder_fast,
                         cudaFuncAttributeMaxDynamicSharedMemorySize,
                         FAST_SMEM_BYTES);
    cudaFuncSetAttribute(exact_chunk,
                         cudaFuncAttributeMaxDynamicSharedMemorySize,
                         EX_SMEM_BYTES);

    float* out_zq  = (float*)d_out;
    float* out_idx = (float*)d_out + (size_t)B_SZ*LAT;
    int write_zq = 1, write_idx = 1;
    if (out_size >= B_SZ*(LAT + NQ)) {
    } else if (out_size >= B_SZ*LAT) {
        write_idx = 0;
    } else {
        write_zq = 0;
        out_idx  = (float*)d_out;
    }

    const int total = NBFRAG + KTOT*LAT + NQ*NEMB;
    prep_kernel<<<(total + 255)/256, 256>>>(w2, cb);
    encoder_fast<<<TILES_TOT, 256, FAST_SMEM_BYTES>>>(x, w1, b1, b2);
    rvq_flag<<<B_SZ/8, 256>>>(cb, out_zq, out_idx, write_zq, write_idx);
    exact_chunk<<<TILES_TOT, 256, EX_SMEM_BYTES>>>(x, w1, b1, b2);
    fix_reduce<<<(B_SZ*LAT + 255)/256, 256>>>();
    rvq_fix<<<B_SZ/8, 256>>>(cb, out_zq, out_idx, write_zq, write_idx);
}